// round 7
// baseline (speedup 1.0000x reference)
#include <cuda_runtime.h>

#define NN 10000
#define EE 100000

// ---------------- device scratch (static allocations only) ----------------
__device__ __align__(16) float g_v[NN * 2048];   // v[n][j*64+o]  82 MB
__device__ __align__(16) float g_u[NN * 64];
__device__ __align__(16) float g_r[NN * 64];
__device__ __align__(16) float g_agg[NN * 64];   // zeroed at end of k_node (self-restoring)
__device__ __align__(16) float g_h[EE * 32];     // relu(ea@w1+b1)  12.8 MB
__device__ int g_histsrc[NN];                    // zeroed inside k_scan after read
__device__ int g_cntdst[NN];                     // zeroed at end of k_node
__device__ int g_start[NN + 1];
__device__ int g_cursor[NN];
__device__ int g_order[EE];
__device__ int g_odst[EE];
__device__ __align__(16) float g_A[64 * 64];
__device__ __align__(16) float g_B[64 * 64];
__device__ __align__(16) float g_C[64 * 64];
__device__ __align__(16) float g_dv[64];

// ---------------- launch 1: histogram ----------------
__global__ void k_hist(const int* __restrict__ ei) {
    int e = blockIdx.x * 256 + threadIdx.x;
    if (e < EE) {
        atomicAdd(&g_histsrc[ei[e]], 1);
        atomicAdd(&g_cntdst[ei[EE + e]], 1);
    }
}

// ---------------- launch 2: exclusive scan (warp-shuffle, 2 barriers) ----------------
__global__ void k_scan() {
    __shared__ int wsum[32];
    int t = threadIdx.x;              // 1024
    int lane = t & 31, wid = t >> 5;
    const int CH = 10;
    int base = t * CH;
    int loc[CH];
    int s = 0;
#pragma unroll
    for (int k = 0; k < CH; k++) {
        int idx = base + k;
        int v = 0;
        if (idx < NN) { v = g_histsrc[idx]; g_histsrc[idx] = 0; }
        loc[k] = s; s += v;
    }
    // warp inclusive scan of s
    int inc = s;
#pragma unroll
    for (int off = 1; off < 32; off <<= 1) {
        int y = __shfl_up_sync(0xffffffffu, inc, off);
        if (lane >= off) inc += y;
    }
    if (lane == 31) wsum[wid] = inc;
    __syncthreads();
    if (wid == 0) {
        int ws = wsum[lane];
#pragma unroll
        for (int off = 1; off < 32; off <<= 1) {
            int y = __shfl_up_sync(0xffffffffu, ws, off);
            if (lane >= off) ws += y;
        }
        wsum[lane] = ws;
    }
    __syncthreads();
    int excl = inc - s + ((wid > 0) ? wsum[wid - 1] : 0);
#pragma unroll
    for (int k = 0; k < CH; k++) {
        int idx = base + k;
        if (idx < NN) {
            int st = excl + loc[k];
            g_start[idx] = st;
            g_cursor[idx] = st;
        }
    }
    if (t == 1023) g_start[NN] = wsum[31];
}

// ---------------- launch 3: scatter edge ids grouped by src ----------------
__global__ void k_scatter(const int* __restrict__ ei) {
    int e = blockIdx.x * 256 + threadIdx.x;
    if (e < EE) {
        int s = ei[e];
        int pos = atomicAdd(&g_cursor[s], 1);
        g_order[pos] = e;
        g_odst[pos] = ei[EE + e];
    }
}

// ---------------- launch 4: fused independent mid work ----------------
// block ranges: v-GEMM | H-GEMM | ur-GEMM | prep
#define MB_V    1256
#define MB_H    (MB_V + 1563)
#define MB_UR   (MB_H + 157)
#define MB_P    (MB_UR + 16)

__global__ void __launch_bounds__(256) k_mid(
    const float* __restrict__ x,  const float* __restrict__ w2,
    const float* __restrict__ b2, const float* __restrict__ root,
    const float* __restrict__ ea, const float* __restrict__ w1,
    const float* __restrict__ b1,
    const float* __restrict__ tw1, const float* __restrict__ tb1,
    const float* __restrict__ tw2, const float* __restrict__ tb2,
    const float* __restrict__ tw3, const float* __restrict__ tb3,
    const float* __restrict__ pw,  const float* __restrict__ pb) {
    __shared__ __align__(16) float4 sbuf4[2560];     // 40 KB union
    int b = blockIdx.x;
    int t = threadIdx.x;

    if (b < MB_V) {
        // ---- v GEMM: v[n][c] = sum_i x[n,i]*w2[c>>6][i*64+(c&63)] ----
        int ct = b & 7;
        int nb = (b >> 3) * 64;
        float4* Wp = sbuf4;                       // [i*64 + c4]
        float*  xT = (float*)(sbuf4 + 2048);      // [i*64 + n]

        const float4* w2f4 = (const float4*)w2;
#pragma unroll
        for (int q = 0; q < 8; q++) {
            int idx = q * 256 + t;
            int i = idx >> 6, c4 = idx & 63;
            int j  = ct * 4 + (c4 >> 4);
            int o4 = c4 & 15;
            Wp[i * 64 + c4] = w2f4[j * 512 + i * 16 + o4];
        }
#pragma unroll
        for (int q = 0; q < 8; q++) {
            int f = q * 256 + t;
            int n = f >> 5, i = f & 31;
            xT[i * 64 + n] = (nb + n < NN) ? x[(nb + n) * 32 + i] : 0.f;
        }
        __syncthreads();

        int ng = t >> 5, cg = t & 31;
        float acc[8][8];
#pragma unroll
        for (int a = 0; a < 8; a++)
#pragma unroll
            for (int c = 0; c < 8; c++) acc[a][c] = 0.f;

#pragma unroll 8
        for (int i = 0; i < 32; i++) {
            float4 xa = *(const float4*)&xT[i * 64 + ng * 8];
            float4 xb = *(const float4*)&xT[i * 64 + ng * 8 + 4];
            float4 wa = Wp[i * 64 + cg];
            float4 wb = Wp[i * 64 + cg + 32];
            float xv[8] = {xa.x, xa.y, xa.z, xa.w, xb.x, xb.y, xb.z, xb.w};
            float wv[8] = {wa.x, wa.y, wa.z, wa.w, wb.x, wb.y, wb.z, wb.w};
#pragma unroll
            for (int a = 0; a < 8; a++)
#pragma unroll
                for (int c = 0; c < 8; c++) acc[a][c] = fmaf(xv[a], wv[c], acc[a][c]);
        }

        float4* vout = (float4*)g_v;
#pragma unroll
        for (int a = 0; a < 8; a++) {
            int n = nb + ng * 8 + a;
            if (n < NN) {
                vout[n * 512 + ct * 64 + cg]      = make_float4(acc[a][0], acc[a][1], acc[a][2], acc[a][3]);
                vout[n * 512 + ct * 64 + cg + 32] = make_float4(acc[a][4], acc[a][5], acc[a][6], acc[a][7]);
            }
        }
    } else if (b < MB_H) {
        // ---- H GEMM: g_h[e][j] = relu(sum_d ea[e,d]*w1[d,j] + b1[j]) ----
        int base = (b - MB_V) * 64;
        float* eas = (float*)sbuf4;              // [64*16]
        float* w1s = eas + 1024;                 // [512]
        float* b1s = w1s + 512;                  // [32]
        for (int q = t; q < 1024; q += 256) {
            int gidx = base * 16 + q;
            eas[q] = (gidx < EE * 16) ? ea[gidx] : 0.f;
        }
        for (int q = t; q < 512; q += 256) w1s[q] = w1[q];
        if (t < 32) b1s[t] = b1[t];
        __syncthreads();
        for (int q = t; q < 2048; q += 256) {
            int el = q >> 5, j = q & 31;
            int e = base + el;
            if (e < EE) {
                float acc = b1s[j];
#pragma unroll
                for (int d = 0; d < 16; d++)
                    acc = fmaf(eas[el * 16 + d], w1s[d * 32 + j], acc);
                g_h[e * 32 + j] = fmaxf(acc, 0.f);
            }
        }
    } else if (b < MB_UR) {
        // ---- u/r GEMM: [64 nodes] x [128 cols: u(64)|r(64)] ----
        int nb = (b - MB_H) * 64;
        float4* Wc = sbuf4;                       // [i*32 + c4], c4<16: b2, else root
        float*  xT = (float*)(sbuf4 + 1024);      // [i*64 + n]
        const float4* b2f4 = (const float4*)b2;
        const float4* rtf4 = (const float4*)root;
#pragma unroll
        for (int q = 0; q < 4; q++) {
            int idx = q * 256 + t;                // [0,1024)
            int i = idx >> 5, c4 = idx & 31;
            Wc[idx] = (c4 < 16) ? b2f4[i * 16 + c4] : rtf4[i * 16 + (c4 - 16)];
        }
#pragma unroll
        for (int q = 0; q < 8; q++) {
            int f = q * 256 + t;
            int n = f >> 5, i = f & 31;
            xT[i * 64 + n] = (nb + n < NN) ? x[(nb + n) * 32 + i] : 0.f;
        }
        __syncthreads();

        int ng = t >> 5, cg = t & 31;
        float acc[8][4];
#pragma unroll
        for (int a = 0; a < 8; a++)
#pragma unroll
            for (int c = 0; c < 4; c++) acc[a][c] = 0.f;

#pragma unroll 8
        for (int i = 0; i < 32; i++) {
            float4 xa = *(const float4*)&xT[i * 64 + ng * 8];
            float4 xb = *(const float4*)&xT[i * 64 + ng * 8 + 4];
            float4 w = Wc[i * 32 + cg];
            float xv[8] = {xa.x, xa.y, xa.z, xa.w, xb.x, xb.y, xb.z, xb.w};
            float wv[4] = {w.x, w.y, w.z, w.w};
#pragma unroll
            for (int a = 0; a < 8; a++)
#pragma unroll
                for (int c = 0; c < 4; c++) acc[a][c] = fmaf(xv[a], wv[c], acc[a][c]);
        }

        float4* u4 = (float4*)g_u;
        float4* r4 = (float4*)g_r;
#pragma unroll
        for (int a = 0; a < 8; a++) {
            int n = nb + ng * 8 + a;
            if (n < NN) {
                float4 val = make_float4(acc[a][0], acc[a][1], acc[a][2], acc[a][3]);
                if (cg < 16) u4[n * 16 + cg] = val;
                else         r4[n * 16 + (cg - 16)] = val;
            }
        }
    } else {
        // ---- prep: fold TCN+proj into A,B,C,dv ----
        int q = (b - MB_UR) * 256 + t;            // [0,4096)
        int c = q >> 6, p = q & 63;
        float a = 0.f, bb = 0.f, cc = 0.f;
        for (int o = 0; o < 64; o++) {
            float pw0 = __ldg(&pw[o * 64 + p]);
            float pw1 = __ldg(&pw[(64 + o) * 64 + p]);
            float pw2 = __ldg(&pw[(128 + o) * 64 + p]);
            bb = fmaf(__ldg(&tw1[o * 192 + c * 3 + 0]), pw0, bb);
            a  = fmaf(__ldg(&tw2[o * 192 + c * 3 + 0]), pw1, a);
            cc = fmaf(__ldg(&tw1[o * 192 + c * 3 + 1]), pw0, cc);
            cc = fmaf(__ldg(&tw2[o * 192 + c * 3 + 1]), pw1, cc);
            cc = fmaf(__ldg(&tw3[o * 192 + c * 3 + 1]), pw2, cc);
        }
        g_A[q] = a; g_B[q] = bb; g_C[q] = cc;
        if (b == MB_UR && t < 64) {
            float d = pb[t];
            for (int o = 0; o < 64; o++) {
                d = fmaf(tb1[o], pw[o * 64 + t], d);
                d = fmaf(tb2[o], pw[(64 + o) * 64 + t], d);
                d = fmaf(tb3[o], pw[(128 + o) * 64 + t], d);
            }
            g_dv[t] = d;
        }
    }
}

// ---------------- launch 5: edge kernel — 4 warps per node (col-half x j-half) ----------------
__global__ void __launch_bounds__(256) k_edge() {
    int t = threadIdx.x;
    int w = t >> 5, l = t & 31;
    int n = blockIdx.x * 2 + (w >> 2);        // grid 5000 -> exactly NN
    int q = w & 3;
    int col = (q & 1) * 32 + l;               // output column
    int jb  = (q >> 1) * 16;                  // j-range base
    int beg = g_start[n], end = g_start[n + 1];
    if (beg == end) return;

    const float* vbase = g_v + n * 2048 + jb * 64 + col;
    float vreg[16];
#pragma unroll
    for (int j = 0; j < 16; j++) vreg[j] = __ldg(&vbase[j * 64]);
    float u = (jb == 0) ? __ldg(&g_u[n * 64 + col]) : 0.f;

    int hoff = jb + (l & 15);
    float h0 = __ldg(&g_h[g_order[beg] * 32 + hoff]);
    float h1 = (beg + 1 < end) ? __ldg(&g_h[g_order[beg + 1] * 32 + hoff]) : 0.f;

    for (int p = beg; p < end; p++) {
        int dn = g_odst[p];
        float h2 = (p + 2 < end) ? __ldg(&g_h[g_order[p + 2] * 32 + hoff]) : 0.f;
        float m0 = u, m1 = 0.f, m2 = 0.f, m3 = 0.f;
#pragma unroll
        for (int j = 0; j < 16; j += 4) {
            float a0 = __shfl_sync(0xffffffffu, h0, j);
            float a1 = __shfl_sync(0xffffffffu, h0, j + 1);
            float a2 = __shfl_sync(0xffffffffu, h0, j + 2);
            float a3 = __shfl_sync(0xffffffffu, h0, j + 3);
            m0 = fmaf(a0, vreg[j],     m0);
            m1 = fmaf(a1, vreg[j + 1], m1);
            m2 = fmaf(a2, vreg[j + 2], m2);
            m3 = fmaf(a3, vreg[j + 3], m3);
        }
        float m = (m0 + m1) + (m2 + m3);
        asm volatile("red.global.add.f32 [%0], %1;"
                     :: "l"(g_agg + dn * 64 + col), "f"(m) : "memory");
        h0 = h1; h1 = h2;
    }
}

// ---------------- launch 6: node kernel ----------------
__global__ void k_node(const float* __restrict__ hprev, const float* __restrict__ bias,
                       float* __restrict__ hout, float* __restrict__ hhist) {
    __shared__ float hs0[64 * 52];
    __shared__ float hs1[64 * 52];
    __shared__ float hs2[64 * 52];
    int t = threadIdx.x;              // 192 threads
    int nb = blockIdx.x * 48;

    for (int s = 0; s < 16; s++) {
        int q = s * 192 + t;
        int nl = q >> 6, o = q & 63;
        int n = nb + nl;
        float hp1 = 0.f, hp2 = 0.f, hg = 0.f;
        if (n < NN) {
            hp1 = hprev[n * 192 + 64 + o];
            hp2 = hprev[n * 192 + 128 + o];
            float cnt = (float)g_cntdst[n];
            float mean = g_agg[n * 64 + o] / fmaxf(cnt, 1.f);
            hg = fmaxf(mean + g_r[n * 64 + o] + bias[o], 0.f);
            hhist[n * 192 + o] = hp1;
            hhist[n * 192 + 64 + o] = hp2;
            hhist[n * 192 + 128 + o] = hg;
        }
        hs0[o * 52 + nl] = hp1;
        hs1[o * 52 + nl] = hp2;
        hs2[o * 52 + nl] = hg;
    }
    __syncthreads();

    // restore invariants for next replay
    for (int q = t; q < 48 * 64; q += 192) {
        int n = nb + (q >> 6);
        if (n < NN) g_agg[n * 64 + (q & 63)] = 0.f;
    }
    if (t < 48 && nb + t < NN) g_cntdst[nb + t] = 0;

    int tn = t % 12, tp = t / 12;
    int n0 = tn * 4, p0 = tp * 4;
    float4 dv = *(const float4*)&g_dv[p0];
    float acc[4][4];
#pragma unroll
    for (int a = 0; a < 4; a++) {
        acc[a][0] = dv.x; acc[a][1] = dv.y; acc[a][2] = dv.z; acc[a][3] = dv.w;
    }

#pragma unroll 8
    for (int c = 0; c < 64; c++) {
        float4 h0 = *(const float4*)&hs0[c * 52 + n0];
        float4 h1 = *(const float4*)&hs1[c * 52 + n0];
        float4 h2 = *(const float4*)&hs2[c * 52 + n0];
        float4 av = __ldg((const float4*)(g_A + c * 64 + p0));
        float4 bv = __ldg((const float4*)(g_B + c * 64 + p0));
        float4 cv = __ldg((const float4*)(g_C + c * 64 + p0));
        float h0v[4] = {h0.x, h0.y, h0.z, h0.w};
        float h1v[4] = {h1.x, h1.y, h1.z, h1.w};
        float h2v[4] = {h2.x, h2.y, h2.z, h2.w};
        float avv[4] = {av.x, av.y, av.z, av.w};
        float bvv[4] = {bv.x, bv.y, bv.z, bv.w};
        float cvv[4] = {cv.x, cv.y, cv.z, cv.w};
#pragma unroll
        for (int a = 0; a < 4; a++)
#pragma unroll
            for (int c2 = 0; c2 < 4; c2++) {
                acc[a][c2] = fmaf(h0v[a], avv[c2], acc[a][c2]);
                acc[a][c2] = fmaf(h1v[a], bvv[c2], acc[a][c2]);
                acc[a][c2] = fmaf(h2v[a], cvv[c2], acc[a][c2]);
            }
    }

#pragma unroll
    for (int a = 0; a < 4; a++) {
        int n = nb + n0 + a;
        if (n < NN)
            *(float4*)&hout[n * 64 + p0] = make_float4(acc[a][0], acc[a][1], acc[a][2], acc[a][3]);
    }
}

// ---------------- launch ----------------
extern "C" void kernel_launch(void* const* d_in, const int* in_sizes, int n_in,
                              void* d_out, int out_size) {
    const float* x     = (const float*)d_in[0];
    const float* ea    = (const float*)d_in[1];
    const float* hprev = (const float*)d_in[2];
    const int*   ei    = (const int*)  d_in[3];
    const float* w1    = (const float*)d_in[4];
    const float* b1    = (const float*)d_in[5];
    const float* w2    = (const float*)d_in[6];
    const float* b2    = (const float*)d_in[7];
    const float* root  = (const float*)d_in[8];
    const float* bias  = (const float*)d_in[9];
    const float* tw1   = (const float*)d_in[10];
    const float* tb1   = (const float*)d_in[11];
    const float* tw2   = (const float*)d_in[12];
    const float* tb2   = (const float*)d_in[13];
    const float* tw3   = (const float*)d_in[14];
    const float* tb3   = (const float*)d_in[15];
    const float* pw    = (const float*)d_in[16];
    const float* pb    = (const float*)d_in[17];

    float* hout  = (float*)d_out;            // [N,64]
    float* hhist = hout + NN * 64;           // [N,3,64]

    k_hist<<<(EE + 255) / 256, 256>>>(ei);
    k_scan<<<1, 1024>>>();
    k_scatter<<<(EE + 255) / 256, 256>>>(ei);
    k_mid<<<MB_P, 256>>>(x, w2, b2, root, ea, w1, b1,
                         tw1, tb1, tw2, tb2, tw3, tb3, pw, pb);
    k_edge<<<5000, 256>>>();
    k_node<<<209, 192>>>(hprev, bias, hout, hhist);
}

// round 8
// speedup vs baseline: 1.2049x; 1.2049x over previous
#include <cuda_runtime.h>
#include <cuda_bf16.h>

#define NN 10000
#define EE 100000

// ---------------- device scratch (static allocations only) ----------------
__device__ __align__(16) float g_v[NN * 2048];   // v[n][j*64+o]  82 MB
__device__ __align__(16) float g_u[NN * 64];
__device__ __align__(16) float g_r[NN * 64];
__device__ __align__(16) float g_agg[NN * 64];   // zeroed at end of k_node (self-restoring)
__device__ __align__(16) float g_h[EE * 32];     // relu(ea@w1+b1)  12.8 MB
__device__ int g_histsrc[NN];                    // zeroed inside k_scan after read
__device__ int g_cntdst[NN];                     // zeroed at end of k_node
__device__ int g_start[NN + 1];
__device__ int g_cursor[NN];
__device__ int g_order[EE];
__device__ int g_odst[EE];
__device__ __align__(16) float g_A[64 * 64];
__device__ __align__(16) float g_B[64 * 64];
__device__ __align__(16) float g_C[64 * 64];
__device__ __align__(16) float g_dv[64];
// bf16-split operands for the v MMA (filled in k_hist, consumed in k_mid)
__device__ __align__(16) unsigned g_xhi[NN * 16];     // x k-pairs, hi
__device__ __align__(16) unsigned g_xlo[NN * 16];     // x k-pairs, lo
__device__ __align__(16) unsigned g_whi[2048 * 16];   // W'[k][c] k-pairs per col, hi
__device__ __align__(16) unsigned g_wlo[2048 * 16];   // lo

__device__ __forceinline__ unsigned pack_bf16(__nv_bfloat16 a, __nv_bfloat16 b) {
    __nv_bfloat162 p = __halves2bfloat162(a, b);     // a in low 16 bits
    return *(unsigned*)&p;
}

__device__ __forceinline__ void mma_bf16(float* acc, const unsigned* a, unsigned b0, unsigned b1) {
    asm volatile(
        "mma.sync.aligned.m16n8k16.row.col.f32.bf16.bf16.f32 "
        "{%0,%1,%2,%3}, {%4,%5,%6,%7}, {%8,%9}, {%0,%1,%2,%3};"
        : "+f"(acc[0]), "+f"(acc[1]), "+f"(acc[2]), "+f"(acc[3])
        : "r"(a[0]), "r"(a[1]), "r"(a[2]), "r"(a[3]), "r"(b0), "r"(b1));
}

// ---------------- launch 1: histogram + bf16 operand pre-split ----------------
// blocks [0,391): histogram; [391, 391+754): split x and W'
__global__ void k_hist(const int* __restrict__ ei, const float* __restrict__ x,
                       const float* __restrict__ w2) {
    int b = blockIdx.x;
    int t = threadIdx.x;
    if (b < 391) {
        int e = b * 256 + t;
        if (e < EE) {
            atomicAdd(&g_histsrc[ei[e]], 1);
            atomicAdd(&g_cntdst[ei[EE + e]], 1);
        }
        return;
    }
    int idx = (b - 391) * 256 + t;
    if (idx < NN * 16) {
        // x pairs: xhi[n*16+kp] = pack(x[n][2kp], x[n][2kp+1])
        int n = idx >> 4, kp = idx & 15;
        float f0 = x[n * 32 + 2 * kp];
        float f1 = x[n * 32 + 2 * kp + 1];
        __nv_bfloat16 h0 = __float2bfloat16_rn(f0);
        __nv_bfloat16 h1 = __float2bfloat16_rn(f1);
        float l0 = f0 - __bfloat162float(h0);
        float l1 = f1 - __bfloat162float(h1);
        g_xhi[idx] = pack_bf16(h0, h1);
        g_xlo[idx] = pack_bf16(__float2bfloat16_rn(l0), __float2bfloat16_rn(l1));
    } else if (idx < NN * 16 + 2048 * 16) {
        // W' pairs: W'[k][c] = w2[c>>6][k*64 + (c&63)]
        int q = idx - NN * 16;
        int c = q >> 4, kp = q & 15;
        int j = c >> 6, o = c & 63;
        float f0 = w2[j * 2048 + (2 * kp) * 64 + o];
        float f1 = w2[j * 2048 + (2 * kp + 1) * 64 + o];
        __nv_bfloat16 h0 = __float2bfloat16_rn(f0);
        __nv_bfloat16 h1 = __float2bfloat16_rn(f1);
        float l0 = f0 - __bfloat162float(h0);
        float l1 = f1 - __bfloat162float(h1);
        g_whi[q] = pack_bf16(h0, h1);
        g_wlo[q] = pack_bf16(__float2bfloat16_rn(l0), __float2bfloat16_rn(l1));
    }
}

// ---------------- launch 2: exclusive scan (warp-shuffle) ----------------
__global__ void k_scan() {
    __shared__ int wsum[32];
    int t = threadIdx.x;              // 1024
    int lane = t & 31, wid = t >> 5;
    const int CH = 10;
    int base = t * CH;
    int loc[CH];
    int s = 0;
#pragma unroll
    for (int k = 0; k < CH; k++) {
        int idx = base + k;
        int v = 0;
        if (idx < NN) { v = g_histsrc[idx]; g_histsrc[idx] = 0; }
        loc[k] = s; s += v;
    }
    int inc = s;
#pragma unroll
    for (int off = 1; off < 32; off <<= 1) {
        int y = __shfl_up_sync(0xffffffffu, inc, off);
        if (lane >= off) inc += y;
    }
    if (lane == 31) wsum[wid] = inc;
    __syncthreads();
    if (wid == 0) {
        int ws = wsum[lane];
#pragma unroll
        for (int off = 1; off < 32; off <<= 1) {
            int y = __shfl_up_sync(0xffffffffu, ws, off);
            if (lane >= off) ws += y;
        }
        wsum[lane] = ws;
    }
    __syncthreads();
    int excl = inc - s + ((wid > 0) ? wsum[wid - 1] : 0);
#pragma unroll
    for (int k = 0; k < CH; k++) {
        int idx = base + k;
        if (idx < NN) {
            int st = excl + loc[k];
            g_start[idx] = st;
            g_cursor[idx] = st;
        }
    }
    if (t == 1023) g_start[NN] = wsum[31];
}

// ---------------- launch 3: scatter edge ids grouped by src ----------------
__global__ void k_scatter(const int* __restrict__ ei) {
    int e = blockIdx.x * 256 + threadIdx.x;
    if (e < EE) {
        int s = ei[e];
        int pos = atomicAdd(&g_cursor[s], 1);
        g_order[pos] = e;
        g_odst[pos] = ei[EE + e];
    }
}

// ---------------- launch 4: fused mid work: v-MMA | H | ur | prep ----------------
#define MB_V    2512                 // 157 node-chunks(64) x 16 col-tiles(128)
#define MB_H    (MB_V + 1563)
#define MB_UR   (MB_H + 157)
#define MB_P    (MB_UR + 16)

__global__ void __launch_bounds__(256) k_mid(
    const float* __restrict__ x,  const float* __restrict__ b2,
    const float* __restrict__ root,
    const float* __restrict__ ea, const float* __restrict__ w1,
    const float* __restrict__ b1,
    const float* __restrict__ tw1, const float* __restrict__ tb1,
    const float* __restrict__ tw2, const float* __restrict__ tb2,
    const float* __restrict__ tw3, const float* __restrict__ tb3,
    const float* __restrict__ pw,  const float* __restrict__ pb) {
    __shared__ __align__(16) unsigned sbuf[7872];    // 31.5 KB union
    int b = blockIdx.x;
    int t = threadIdx.x;

    if (b < MB_V) {
        // ---- v via split-bf16 mma: block = 64 nodes x 128 cols ----
        int ct16 = b & 15;                 // col tile: cols ct16*128..+128
        int nb = (b >> 4) * 64;            // node base
        int cb = ct16 * 128;
        unsigned* xsh = sbuf;              // [64][20]
        unsigned* xsl = sbuf + 1280;       // [64][20]
        unsigned* wsh = sbuf + 2560;       // [128][20]
        unsigned* wsl = sbuf + 5120;       // [128][20]

        for (int q = t; q < 1024; q += 256) {
            int r = q >> 4, kp = q & 15;
            int n = nb + r;
            unsigned vh = 0, vl = 0;
            if (n < NN) { vh = g_xhi[n * 16 + kp]; vl = g_xlo[n * 16 + kp]; }
            xsh[r * 20 + kp] = vh;
            xsl[r * 20 + kp] = vl;
        }
        for (int q = t; q < 2048; q += 256) {
            int c = q >> 4, kp = q & 15;
            wsh[c * 20 + kp] = g_whi[(cb + c) * 16 + kp];
            wsl[c * 20 + kp] = g_wlo[(cb + c) * 16 + kp];
        }
        __syncthreads();

        int w = t >> 5, l = t & 31;
        int wn = w >> 1;                   // node group [0,4): rows wn*16..+16
        int wc = w & 1;                    // col half: cols wc*64..+64
        int r = wn * 16 + (l >> 2);        // fragment row (and r+8)
        int cq = l & 3;

        float acc[8][4];
#pragma unroll
        for (int ct = 0; ct < 8; ct++)
#pragma unroll
            for (int q = 0; q < 4; q++) acc[ct][q] = 0.f;

#pragma unroll
        for (int ks = 0; ks < 2; ks++) {
            int kb = ks * 8 + cq;
            unsigned ah[4], al[4];
            ah[0] = xsh[r * 20 + kb];       ah[1] = xsh[(r + 8) * 20 + kb];
            ah[2] = xsh[r * 20 + kb + 4];   ah[3] = xsh[(r + 8) * 20 + kb + 4];
            al[0] = xsl[r * 20 + kb];       al[1] = xsl[(r + 8) * 20 + kb];
            al[2] = xsl[r * 20 + kb + 4];   al[3] = xsl[(r + 8) * 20 + kb + 4];
#pragma unroll
            for (int ct = 0; ct < 8; ct++) {
                int c = wc * 64 + ct * 8 + (l >> 2);
                unsigned bh0 = wsh[c * 20 + kb], bh1 = wsh[c * 20 + kb + 4];
                unsigned bl0 = wsl[c * 20 + kb], bl1 = wsl[c * 20 + kb + 4];
                mma_bf16(acc[ct], ah, bh0, bh1);   // hi*hi
                mma_bf16(acc[ct], ah, bl0, bl1);   // hi*lo
                mma_bf16(acc[ct], al, bh0, bh1);   // lo*hi
            }
        }

        int rr = nb + wn * 16 + (l >> 2);
#pragma unroll
        for (int ct = 0; ct < 8; ct++) {
            int col = cb + wc * 64 + ct * 8 + 2 * cq;
            if (rr < NN)
                *(float2*)&g_v[rr * 2048 + col] = make_float2(acc[ct][0], acc[ct][1]);
            if (rr + 8 < NN)
                *(float2*)&g_v[(rr + 8) * 2048 + col] = make_float2(acc[ct][2], acc[ct][3]);
        }
    } else if (b < MB_H) {
        // ---- H GEMM: g_h[e][j] = relu(sum_d ea[e,d]*w1[d,j] + b1[j]) ----
        int base = (b - MB_V) * 64;
        float* eas = (float*)sbuf;               // [64*16]
        float* w1s = eas + 1024;                 // [512]
        float* b1s = w1s + 512;                  // [32]
        for (int q = t; q < 1024; q += 256) {
            int gidx = base * 16 + q;
            eas[q] = (gidx < EE * 16) ? ea[gidx] : 0.f;
        }
        for (int q = t; q < 512; q += 256) w1s[q] = w1[q];
        if (t < 32) b1s[t] = b1[t];
        __syncthreads();
        for (int q = t; q < 2048; q += 256) {
            int el = q >> 5, j = q & 31;
            int e = base + el;
            if (e < EE) {
                float acc = b1s[j];
#pragma unroll
                for (int d = 0; d < 16; d++)
                    acc = fmaf(eas[el * 16 + d], w1s[d * 32 + j], acc);
                g_h[e * 32 + j] = fmaxf(acc, 0.f);
            }
        }
    } else if (b < MB_UR) {
        // ---- u/r GEMM: [64 nodes] x [128 cols: u(64)|r(64)] ----
        int nb = (b - MB_H) * 64;
        float4* Wc = (float4*)sbuf;               // 1024 float4
        float*  xT = (float*)sbuf + 4096;         // [i*64 + n]
        const float4* b2f4 = (const float4*)b2;
        const float4* rtf4 = (const float4*)root;
#pragma unroll
        for (int q = 0; q < 4; q++) {
            int idx = q * 256 + t;
            int i = idx >> 5, c4 = idx & 31;
            Wc[idx] = (c4 < 16) ? b2f4[i * 16 + c4] : rtf4[i * 16 + (c4 - 16)];
        }
#pragma unroll
        for (int q = 0; q < 8; q++) {
            int f = q * 256 + t;
            int n = f >> 5, i = f & 31;
            xT[i * 64 + n] = (nb + n < NN) ? x[(nb + n) * 32 + i] : 0.f;
        }
        __syncthreads();

        int ng = t >> 5, cg = t & 31;
        float acc[8][4];
#pragma unroll
        for (int a = 0; a < 8; a++)
#pragma unroll
            for (int c = 0; c < 4; c++) acc[a][c] = 0.f;

#pragma unroll 8
        for (int i = 0; i < 32; i++) {
            float4 xa = *(const float4*)&xT[i * 64 + ng * 8];
            float4 xb = *(const float4*)&xT[i * 64 + ng * 8 + 4];
            float4 wv4 = Wc[i * 32 + cg];
            float xv[8] = {xa.x, xa.y, xa.z, xa.w, xb.x, xb.y, xb.z, xb.w};
            float wv[4] = {wv4.x, wv4.y, wv4.z, wv4.w};
#pragma unroll
            for (int a = 0; a < 8; a++)
#pragma unroll
                for (int c = 0; c < 4; c++) acc[a][c] = fmaf(xv[a], wv[c], acc[a][c]);
        }

        float4* u4 = (float4*)g_u;
        float4* r4 = (float4*)g_r;
#pragma unroll
        for (int a = 0; a < 8; a++) {
            int n = nb + ng * 8 + a;
            if (n < NN) {
                float4 val = make_float4(acc[a][0], acc[a][1], acc[a][2], acc[a][3]);
                if (cg < 16) u4[n * 16 + cg] = val;
                else         r4[n * 16 + (cg - 16)] = val;
            }
        }
    } else {
        // ---- prep: fold TCN+proj into A,B,C,dv ----
        int q = (b - MB_UR) * 256 + t;            // [0,4096)
        int c = q >> 6, p = q & 63;
        float a = 0.f, bb = 0.f, cc = 0.f;
        for (int o = 0; o < 64; o++) {
            float pw0 = __ldg(&pw[o * 64 + p]);
            float pw1 = __ldg(&pw[(64 + o) * 64 + p]);
            float pw2 = __ldg(&pw[(128 + o) * 64 + p]);
            bb = fmaf(__ldg(&tw1[o * 192 + c * 3 + 0]), pw0, bb);
            a  = fmaf(__ldg(&tw2[o * 192 + c * 3 + 0]), pw1, a);
            cc = fmaf(__ldg(&tw1[o * 192 + c * 3 + 1]), pw0, cc);
            cc = fmaf(__ldg(&tw2[o * 192 + c * 3 + 1]), pw1, cc);
            cc = fmaf(__ldg(&tw3[o * 192 + c * 3 + 1]), pw2, cc);
        }
        g_A[q] = a; g_B[q] = bb; g_C[q] = cc;
        if (b == MB_UR && t < 64) {
            float d = pb[t];
            for (int o = 0; o < 64; o++) {
                d = fmaf(tb1[o], pw[o * 64 + t], d);
                d = fmaf(tb2[o], pw[(64 + o) * 64 + t], d);
                d = fmaf(tb3[o], pw[(128 + o) * 64 + t], d);
            }
            g_dv[t] = d;
        }
    }
}

// ---------------- launch 5: edge kernel — 2 warps/node, depth-2 prefetch (R5 shape) ----------------
__global__ void __launch_bounds__(128) k_edge() {
    int t = threadIdx.x;
    int w = t >> 5, l = t & 31;
    int n = blockIdx.x * 2 + (w >> 1);        // grid 5000 -> exactly NN
    int half = w & 1;
    int col = half * 32 + l;
    int beg = g_start[n], end = g_start[n + 1];
    if (beg == end) return;

    const float* vbase = g_v + n * 2048 + col;
    float vreg[32];
#pragma unroll
    for (int j = 0; j < 32; j++) vreg[j] = __ldg(&vbase[j * 64]);
    float u = __ldg(&g_u[n * 64 + col]);

    float h0 = __ldg(&g_h[g_order[beg] * 32 + l]);
    float h1 = (beg + 1 < end) ? __ldg(&g_h[g_order[beg + 1] * 32 + l]) : 0.f;

    for (int p = beg; p < end; p++) {
        int dn = g_odst[p];
        float h2 = (p + 2 < end) ? __ldg(&g_h[g_order[p + 2] * 32 + l]) : 0.f;
        float m0 = u, m1 = 0.f, m2 = 0.f, m3 = 0.f;
#pragma unroll
        for (int j = 0; j < 32; j += 4) {
            float a0 = __shfl_sync(0xffffffffu, h0, j);
            float a1 = __shfl_sync(0xffffffffu, h0, j + 1);
            float a2 = __shfl_sync(0xffffffffu, h0, j + 2);
            float a3 = __shfl_sync(0xffffffffu, h0, j + 3);
            m0 = fmaf(a0, vreg[j],     m0);
            m1 = fmaf(a1, vreg[j + 1], m1);
            m2 = fmaf(a2, vreg[j + 2], m2);
            m3 = fmaf(a3, vreg[j + 3], m3);
        }
        float m = (m0 + m1) + (m2 + m3);
        asm volatile("red.global.add.f32 [%0], %1;"
                     :: "l"(g_agg + dn * 64 + col), "f"(m) : "memory");
        h0 = h1; h1 = h2;
    }
}

// ---------------- launch 6: node kernel ----------------
__global__ void k_node(const float* __restrict__ hprev, const float* __restrict__ bias,
                       float* __restrict__ hout, float* __restrict__ hhist) {
    __shared__ float hs0[64 * 52];
    __shared__ float hs1[64 * 52];
    __shared__ float hs2[64 * 52];
    int t = threadIdx.x;              // 192 threads
    int nb = blockIdx.x * 48;

    for (int s = 0; s < 16; s++) {
        int q = s * 192 + t;
        int nl = q >> 6, o = q & 63;
        int n = nb + nl;
        float hp1 = 0.f, hp2 = 0.f, hg = 0.f;
        if (n < NN) {
            hp1 = hprev[n * 192 + 64 + o];
            hp2 = hprev[n * 192 + 128 + o];
            float cnt = (float)g_cntdst[n];
            float mean = g_agg[n * 64 + o] / fmaxf(cnt, 1.f);
            hg = fmaxf(mean + g_r[n * 64 + o] + bias[o], 0.f);
            hhist[n * 192 + o] = hp1;
            hhist[n * 192 + 64 + o] = hp2;
            hhist[n * 192 + 128 + o] = hg;
        }
        hs0[o * 52 + nl] = hp1;
        hs1[o * 52 + nl] = hp2;
        hs2[o * 52 + nl] = hg;
    }
    __syncthreads();

    // restore invariants for next replay
    for (int q = t; q < 48 * 64; q += 192) {
        int n = nb + (q >> 6);
        if (n < NN) g_agg[n * 64 + (q & 63)] = 0.f;
    }
    if (t < 48 && nb + t < NN) g_cntdst[nb + t] = 0;

    int tn = t % 12, tp = t / 12;
    int n0 = tn * 4, p0 = tp * 4;
    float4 dv = *(const float4*)&g_dv[p0];
    float acc[4][4];
#pragma unroll
    for (int a = 0; a < 4; a++) {
        acc[a][0] = dv.x; acc[a][1] = dv.y; acc[a][2] = dv.z; acc[a][3] = dv.w;
    }

#pragma unroll 8
    for (int c = 0; c < 64; c++) {
        float4 h0 = *(const float4*)&hs0[c * 52 + n0];
        float4 h1 = *(const float4*)&hs1[c * 52 + n0];
        float4 h2 = *(const float4*)&hs2[c * 52 + n0];
        float4 av = __ldg((const float4*)(g_A + c * 64 + p0));
        float4 bv = __ldg((const float4*)(g_B + c * 64 + p0));
        float4 cv = __ldg((const float4*)(g_C + c * 64 + p0));
        float h0v[4] = {h0.x, h0.y, h0.z, h0.w};
        float h1v[4] = {h1.x, h1.y, h1.z, h1.w};
        float h2v[4] = {h2.x, h2.y, h2.z, h2.w};
        float avv[4] = {av.x, av.y, av.z, av.w};
        float bvv[4] = {bv.x, bv.y, bv.z, bv.w};
        float cvv[4] = {cv.x, cv.y, cv.z, cv.w};
#pragma unroll
        for (int a = 0; a < 4; a++)
#pragma unroll
            for (int c2 = 0; c2 < 4; c2++) {
                acc[a][c2] = fmaf(h0v[a], avv[c2], acc[a][c2]);
                acc[a][c2] = fmaf(h1v[a], bvv[c2], acc[a][c2]);
                acc[a][c2] = fmaf(h2v[a], cvv[c2], acc[a][c2]);
            }
    }

#pragma unroll
    for (int a = 0; a < 4; a++) {
        int n = nb + n0 + a;
        if (n < NN)
            *(float4*)&hout[n * 64 + p0] = make_float4(acc[a][0], acc[a][1], acc[a][2], acc[a][3]);
    }
}

// ---------------- launch ----------------
extern "C" void kernel_launch(void* const* d_in, const int* in_sizes, int n_in,
                              void* d_out, int out_size) {
    const float* x     = (const float*)d_in[0];
    const float* ea    = (const float*)d_in[1];
    const float* hprev = (const float*)d_in[2];
    const int*   ei    = (const int*)  d_in[3];
    const float* w1    = (const float*)d_in[4];
    const float* b1    = (const float*)d_in[5];
    const float* w2    = (const float*)d_in[6];
    const float* b2    = (const float*)d_in[7];
    const float* root  = (const float*)d_in[8];
    const float* bias  = (const float*)d_in[9];
    const float* tw1   = (const float*)d_in[10];
    const float* tb1   = (const float*)d_in[11];
    const float* tw2   = (const float*)d_in[12];
    const float* tb2   = (const float*)d_in[13];
    const float* tw3   = (const float*)d_in[14];
    const float* tb3   = (const float*)d_in[15];
    const float* pw    = (const float*)d_in[16];
    const float* pb    = (const float*)d_in[17];

    float* hout  = (float*)d_out;            // [N,64]
    float* hhist = hout + NN * 64;           // [N,3,64]

    // 391 hist blocks + ceil((160000+32768)/256)=754 split blocks
    k_hist<<<391 + 754, 256>>>(ei, x, w2);
    k_scan<<<1, 1024>>>();
    k_scatter<<<(EE + 255) / 256, 256>>>(ei);
    k_mid<<<MB_P, 256>>>(x, b2, root, ea, w1, b1,
                         tw1, tb1, tw2, tb2, tw3, tb3, pw, pb);
    k_edge<<<5000, 128>>>();
    k_node<<<209, 192>>>(hprev, bias, hout, hhist);
}

// round 9
// speedup vs baseline: 1.3496x; 1.1201x over previous
#include <cuda_runtime.h>
#include <cuda_bf16.h>

#define NN 10000
#define EE 100000

// ---------------- device scratch (static allocations only) ----------------
__device__ __align__(16) float g_v[NN * 2048];   // v[n][j*64+o]  82 MB
__device__ __align__(16) float g_u[NN * 64];
__device__ __align__(16) float g_r[NN * 64];
__device__ __align__(16) float g_agg[NN * 64];   // zeroed at end of k_node (self-restoring)
__device__ __align__(16) float g_h[EE * 32];     // relu(ea@w1+b1)  12.8 MB
__device__ int g_histsrc[NN];                    // zeroed inside k_scan after read
__device__ int g_cntdst[NN];                     // zeroed at end of k_node
__device__ int g_start[NN + 1];
__device__ int g_cursor[NN];
__device__ int g_order[EE];
__device__ int g_odst[EE];
__device__ __align__(16) float g_A[64 * 64];
__device__ __align__(16) float g_B[64 * 64];
__device__ __align__(16) float g_C[64 * 64];
__device__ __align__(16) float g_dv[64];
// bf16-split operands for the v MMA
__device__ __align__(16) unsigned g_xhi[NN * 16];
__device__ __align__(16) unsigned g_xlo[NN * 16];
__device__ __align__(16) unsigned g_whi[2048 * 16];
__device__ __align__(16) unsigned g_wlo[2048 * 16];

__device__ __forceinline__ unsigned pack_bf16(__nv_bfloat16 a, __nv_bfloat16 b) {
    __nv_bfloat162 p = __halves2bfloat162(a, b);     // a in low 16 bits
    return *(unsigned*)&p;
}

__device__ __forceinline__ void mma_bf16(float* acc, const unsigned* a, unsigned b0, unsigned b1) {
    asm volatile(
        "mma.sync.aligned.m16n8k16.row.col.f32.bf16.bf16.f32 "
        "{%0,%1,%2,%3}, {%4,%5,%6,%7}, {%8,%9}, {%0,%1,%2,%3};"
        : "+f"(acc[0]), "+f"(acc[1]), "+f"(acc[2]), "+f"(acc[3])
        : "r"(a[0]), "r"(a[1]), "r"(a[2]), "r"(a[3]), "r"(b0), "r"(b1));
}

// ---------------- stream A-1: histogram ----------------
__global__ void k_hist(const int* __restrict__ ei) {
    int e = blockIdx.x * 256 + threadIdx.x;
    if (e < EE) {
        atomicAdd(&g_histsrc[ei[e]], 1);
        atomicAdd(&g_cntdst[ei[EE + e]], 1);
    }
}

// ---------------- stream B-1: bf16 operand pre-split ----------------
__global__ void k_split(const float* __restrict__ x, const float* __restrict__ w2) {
    int idx = blockIdx.x * 256 + threadIdx.x;
    if (idx < NN * 16) {
        int n = idx >> 4, kp = idx & 15;
        float f0 = x[n * 32 + 2 * kp];
        float f1 = x[n * 32 + 2 * kp + 1];
        __nv_bfloat16 h0 = __float2bfloat16_rn(f0);
        __nv_bfloat16 h1 = __float2bfloat16_rn(f1);
        float l0 = f0 - __bfloat162float(h0);
        float l1 = f1 - __bfloat162float(h1);
        g_xhi[idx] = pack_bf16(h0, h1);
        g_xlo[idx] = pack_bf16(__float2bfloat16_rn(l0), __float2bfloat16_rn(l1));
    } else if (idx < NN * 16 + 2048 * 16) {
        int q = idx - NN * 16;
        int c = q >> 4, kp = q & 15;
        int j = c >> 6, o = c & 63;
        float f0 = w2[j * 2048 + (2 * kp) * 64 + o];
        float f1 = w2[j * 2048 + (2 * kp + 1) * 64 + o];
        __nv_bfloat16 h0 = __float2bfloat16_rn(f0);
        __nv_bfloat16 h1 = __float2bfloat16_rn(f1);
        float l0 = f0 - __bfloat162float(h0);
        float l1 = f1 - __bfloat162float(h1);
        g_whi[q] = pack_bf16(h0, h1);
        g_wlo[q] = pack_bf16(__float2bfloat16_rn(l0), __float2bfloat16_rn(l1));
    }
}

// ---------------- stream A-2: exclusive scan (warp-shuffle) ----------------
__global__ void k_scan() {
    __shared__ int wsum[32];
    int t = threadIdx.x;              // 1024
    int lane = t & 31, wid = t >> 5;
    const int CH = 10;
    int base = t * CH;
    int loc[CH];
    int s = 0;
#pragma unroll
    for (int k = 0; k < CH; k++) {
        int idx = base + k;
        int v = 0;
        if (idx < NN) { v = g_histsrc[idx]; g_histsrc[idx] = 0; }
        loc[k] = s; s += v;
    }
    int inc = s;
#pragma unroll
    for (int off = 1; off < 32; off <<= 1) {
        int y = __shfl_up_sync(0xffffffffu, inc, off);
        if (lane >= off) inc += y;
    }
    if (lane == 31) wsum[wid] = inc;
    __syncthreads();
    if (wid == 0) {
        int ws = wsum[lane];
#pragma unroll
        for (int off = 1; off < 32; off <<= 1) {
            int y = __shfl_up_sync(0xffffffffu, ws, off);
            if (lane >= off) ws += y;
        }
        wsum[lane] = ws;
    }
    __syncthreads();
    int excl = inc - s + ((wid > 0) ? wsum[wid - 1] : 0);
#pragma unroll
    for (int k = 0; k < CH; k++) {
        int idx = base + k;
        if (idx < NN) {
            int st = excl + loc[k];
            g_start[idx] = st;
            g_cursor[idx] = st;
        }
    }
    if (t == 1023) g_start[NN] = wsum[31];
}

// ---------------- stream A-3: scatter edge ids grouped by src ----------------
__global__ void k_scatter(const int* __restrict__ ei) {
    int e = blockIdx.x * 256 + threadIdx.x;
    if (e < EE) {
        int s = ei[e];
        int pos = atomicAdd(&g_cursor[s], 1);
        g_order[pos] = e;
        g_odst[pos] = ei[EE + e];
    }
}

// ---------------- stream B-2: fused mid work: v-MMA | H | ur | prep ----------------
#define MB_V    2512                 // 157 node-chunks(64) x 16 col-tiles(128)
#define MB_H    (MB_V + 1563)
#define MB_UR   (MB_H + 157)
#define MB_P    (MB_UR + 16)

__global__ void __launch_bounds__(256) k_mid(
    const float* __restrict__ x,  const float* __restrict__ b2,
    const float* __restrict__ root,
    const float* __restrict__ ea, const float* __restrict__ w1,
    const float* __restrict__ b1,
    const float* __restrict__ tw1, const float* __restrict__ tb1,
    const float* __restrict__ tw2, const float* __restrict__ tb2,
    const float* __restrict__ tw3, const float* __restrict__ tb3,
    const float* __restrict__ pw,  const float* __restrict__ pb) {
    __shared__ __align__(16) unsigned sbuf[7872];    // 31.5 KB union
    int b = blockIdx.x;
    int t = threadIdx.x;

    if (b < MB_V) {
        // ---- v via split-bf16 mma: block = 64 nodes x 128 cols ----
        int ct16 = b & 15;
        int nb = (b >> 4) * 64;
        int cb = ct16 * 128;
        unsigned* xsh = sbuf;              // [64][20]
        unsigned* xsl = sbuf + 1280;
        unsigned* wsh = sbuf + 2560;       // [128][20]
        unsigned* wsl = sbuf + 5120;

        for (int q = t; q < 1024; q += 256) {
            int r = q >> 4, kp = q & 15;
            int n = nb + r;
            unsigned vh = 0, vl = 0;
            if (n < NN) { vh = g_xhi[n * 16 + kp]; vl = g_xlo[n * 16 + kp]; }
            xsh[r * 20 + kp] = vh;
            xsl[r * 20 + kp] = vl;
        }
        for (int q = t; q < 2048; q += 256) {
            int c = q >> 4, kp = q & 15;
            wsh[c * 20 + kp] = g_whi[(cb + c) * 16 + kp];
            wsl[c * 20 + kp] = g_wlo[(cb + c) * 16 + kp];
        }
        __syncthreads();

        int w = t >> 5, l = t & 31;
        int wn = w >> 1;
        int wc = w & 1;
        int r = wn * 16 + (l >> 2);
        int cq = l & 3;

        float acc[8][4];
#pragma unroll
        for (int ct = 0; ct < 8; ct++)
#pragma unroll
            for (int q = 0; q < 4; q++) acc[ct][q] = 0.f;

#pragma unroll
        for (int ks = 0; ks < 2; ks++) {
            int kb = ks * 8 + cq;
            unsigned ah[4], al[4];
            ah[0] = xsh[r * 20 + kb];       ah[1] = xsh[(r + 8) * 20 + kb];
            ah[2] = xsh[r * 20 + kb + 4];   ah[3] = xsh[(r + 8) * 20 + kb + 4];
            al[0] = xsl[r * 20 + kb];       al[1] = xsl[(r + 8) * 20 + kb];
            al[2] = xsl[r * 20 + kb + 4];   al[3] = xsl[(r + 8) * 20 + kb + 4];
#pragma unroll
            for (int ct = 0; ct < 8; ct++) {
                int c = wc * 64 + ct * 8 + (l >> 2);
                unsigned bh0 = wsh[c * 20 + kb], bh1 = wsh[c * 20 + kb + 4];
                unsigned bl0 = wsl[c * 20 + kb], bl1 = wsl[c * 20 + kb + 4];
                mma_bf16(acc[ct], ah, bh0, bh1);
                mma_bf16(acc[ct], ah, bl0, bl1);
                mma_bf16(acc[ct], al, bh0, bh1);
            }
        }

        int rr = nb + wn * 16 + (l >> 2);
#pragma unroll
        for (int ct = 0; ct < 8; ct++) {
            int col = cb + wc * 64 + ct * 8 + 2 * cq;
            if (rr < NN)
                *(float2*)&g_v[rr * 2048 + col] = make_float2(acc[ct][0], acc[ct][1]);
            if (rr + 8 < NN)
                *(float2*)&g_v[(rr + 8) * 2048 + col] = make_float2(acc[ct][2], acc[ct][3]);
        }
    } else if (b < MB_H) {
        // ---- H GEMM ----
        int base = (b - MB_V) * 64;
        float* eas = (float*)sbuf;
        float* w1s = eas + 1024;
        float* b1s = w1s + 512;
        for (int q = t; q < 1024; q += 256) {
            int gidx = base * 16 + q;
            eas[q] = (gidx < EE * 16) ? ea[gidx] : 0.f;
        }
        for (int q = t; q < 512; q += 256) w1s[q] = w1[q];
        if (t < 32) b1s[t] = b1[t];
        __syncthreads();
        for (int q = t; q < 2048; q += 256) {
            int el = q >> 5, j = q & 31;
            int e = base + el;
            if (e < EE) {
                float acc = b1s[j];
#pragma unroll
                for (int d = 0; d < 16; d++)
                    acc = fmaf(eas[el * 16 + d], w1s[d * 32 + j], acc);
                g_h[e * 32 + j] = fmaxf(acc, 0.f);
            }
        }
    } else if (b < MB_UR) {
        // ---- u/r GEMM ----
        int nb = (b - MB_H) * 64;
        float4* Wc = (float4*)sbuf;
        float*  xT = (float*)sbuf + 4096;
        const float4* b2f4 = (const float4*)b2;
        const float4* rtf4 = (const float4*)root;
#pragma unroll
        for (int q = 0; q < 4; q++) {
            int idx = q * 256 + t;
            int i = idx >> 5, c4 = idx & 31;
            Wc[idx] = (c4 < 16) ? b2f4[i * 16 + c4] : rtf4[i * 16 + (c4 - 16)];
        }
#pragma unroll
        for (int q = 0; q < 8; q++) {
            int f = q * 256 + t;
            int n = f >> 5, i = f & 31;
            xT[i * 64 + n] = (nb + n < NN) ? x[(nb + n) * 32 + i] : 0.f;
        }
        __syncthreads();

        int ng = t >> 5, cg = t & 31;
        float acc[8][4];
#pragma unroll
        for (int a = 0; a < 8; a++)
#pragma unroll
            for (int c = 0; c < 4; c++) acc[a][c] = 0.f;

#pragma unroll 8
        for (int i = 0; i < 32; i++) {
            float4 xa = *(const float4*)&xT[i * 64 + ng * 8];
            float4 xb = *(const float4*)&xT[i * 64 + ng * 8 + 4];
            float4 wv4 = Wc[i * 32 + cg];
            float xv[8] = {xa.x, xa.y, xa.z, xa.w, xb.x, xb.y, xb.z, xb.w};
            float wv[4] = {wv4.x, wv4.y, wv4.z, wv4.w};
#pragma unroll
            for (int a = 0; a < 8; a++)
#pragma unroll
                for (int c = 0; c < 4; c++) acc[a][c] = fmaf(xv[a], wv[c], acc[a][c]);
        }

        float4* u4 = (float4*)g_u;
        float4* r4 = (float4*)g_r;
#pragma unroll
        for (int a = 0; a < 8; a++) {
            int n = nb + ng * 8 + a;
            if (n < NN) {
                float4 val = make_float4(acc[a][0], acc[a][1], acc[a][2], acc[a][3]);
                if (cg < 16) u4[n * 16 + cg] = val;
                else         r4[n * 16 + (cg - 16)] = val;
            }
        }
    } else {
        // ---- prep: fold TCN+proj into A,B,C,dv ----
        int q = (b - MB_UR) * 256 + t;
        int c = q >> 6, p = q & 63;
        float a = 0.f, bb = 0.f, cc = 0.f;
        for (int o = 0; o < 64; o++) {
            float pw0 = __ldg(&pw[o * 64 + p]);
            float pw1 = __ldg(&pw[(64 + o) * 64 + p]);
            float pw2 = __ldg(&pw[(128 + o) * 64 + p]);
            bb = fmaf(__ldg(&tw1[o * 192 + c * 3 + 0]), pw0, bb);
            a  = fmaf(__ldg(&tw2[o * 192 + c * 3 + 0]), pw1, a);
            cc = fmaf(__ldg(&tw1[o * 192 + c * 3 + 1]), pw0, cc);
            cc = fmaf(__ldg(&tw2[o * 192 + c * 3 + 1]), pw1, cc);
            cc = fmaf(__ldg(&tw3[o * 192 + c * 3 + 1]), pw2, cc);
        }
        g_A[q] = a; g_B[q] = bb; g_C[q] = cc;
        if (b == MB_UR && t < 64) {
            float d = pb[t];
            for (int o = 0; o < 64; o++) {
                d = fmaf(tb1[o], pw[o * 64 + t], d);
                d = fmaf(tb2[o], pw[(64 + o) * 64 + t], d);
                d = fmaf(tb3[o], pw[(128 + o) * 64 + t], d);
            }
            g_dv[t] = d;
        }
    }
}

// ---------------- join: edge kernel — 2 warps/node, depth-2 prefetch ----------------
__global__ void __launch_bounds__(128) k_edge() {
    int t = threadIdx.x;
    int w = t >> 5, l = t & 31;
    int n = blockIdx.x * 2 + (w >> 1);        // grid 5000 -> exactly NN
    int half = w & 1;
    int col = half * 32 + l;
    int beg = g_start[n], end = g_start[n + 1];
    if (beg == end) return;

    const float* vbase = g_v + n * 2048 + col;
    float vreg[32];
#pragma unroll
    for (int j = 0; j < 32; j++) vreg[j] = __ldg(&vbase[j * 64]);
    float u = __ldg(&g_u[n * 64 + col]);

    float h0 = __ldg(&g_h[g_order[beg] * 32 + l]);
    float h1 = (beg + 1 < end) ? __ldg(&g_h[g_order[beg + 1] * 32 + l]) : 0.f;

    for (int p = beg; p < end; p++) {
        int dn = g_odst[p];
        float h2 = (p + 2 < end) ? __ldg(&g_h[g_order[p + 2] * 32 + l]) : 0.f;
        float m0 = u, m1 = 0.f, m2 = 0.f, m3 = 0.f;
#pragma unroll
        for (int j = 0; j < 32; j += 4) {
            float a0 = __shfl_sync(0xffffffffu, h0, j);
            float a1 = __shfl_sync(0xffffffffu, h0, j + 1);
            float a2 = __shfl_sync(0xffffffffu, h0, j + 2);
            float a3 = __shfl_sync(0xffffffffu, h0, j + 3);
            m0 = fmaf(a0, vreg[j],     m0);
            m1 = fmaf(a1, vreg[j + 1], m1);
            m2 = fmaf(a2, vreg[j + 2], m2);
            m3 = fmaf(a3, vreg[j + 3], m3);
        }
        float m = (m0 + m1) + (m2 + m3);
        asm volatile("red.global.add.f32 [%0], %1;"
                     :: "l"(g_agg + dn * 64 + col), "f"(m) : "memory");
        h0 = h1; h1 = h2;
    }
}

// ---------------- final: node kernel ----------------
__global__ void k_node(const float* __restrict__ hprev, const float* __restrict__ bias,
                       float* __restrict__ hout, float* __restrict__ hhist) {
    __shared__ float hs0[64 * 52];
    __shared__ float hs1[64 * 52];
    __shared__ float hs2[64 * 52];
    int t = threadIdx.x;              // 192 threads
    int nb = blockIdx.x * 48;

    for (int s = 0; s < 16; s++) {
        int q = s * 192 + t;
        int nl = q >> 6, o = q & 63;
        int n = nb + nl;
        float hp1 = 0.f, hp2 = 0.f, hg = 0.f;
        if (n < NN) {
            hp1 = hprev[n * 192 + 64 + o];
            hp2 = hprev[n * 192 + 128 + o];
            float cnt = (float)g_cntdst[n];
            float mean = g_agg[n * 64 + o] / fmaxf(cnt, 1.f);
            hg = fmaxf(mean + g_r[n * 64 + o] + bias[o], 0.f);
            hhist[n * 192 + o] = hp1;
            hhist[n * 192 + 64 + o] = hp2;
            hhist[n * 192 + 128 + o] = hg;
        }
        hs0[o * 52 + nl] = hp1;
        hs1[o * 52 + nl] = hp2;
        hs2[o * 52 + nl] = hg;
    }
    __syncthreads();

    // restore invariants for next replay
    for (int q = t; q < 48 * 64; q += 192) {
        int n = nb + (q >> 6);
        if (n < NN) g_agg[n * 64 + (q & 63)] = 0.f;
    }
    if (t < 48 && nb + t < NN) g_cntdst[nb + t] = 0;

    int tn = t % 12, tp = t / 12;
    int n0 = tn * 4, p0 = tp * 4;
    float4 dv = *(const float4*)&g_dv[p0];
    float acc[4][4];
#pragma unroll
    for (int a = 0; a < 4; a++) {
        acc[a][0] = dv.x; acc[a][1] = dv.y; acc[a][2] = dv.z; acc[a][3] = dv.w;
    }

#pragma unroll 8
    for (int c = 0; c < 64; c++) {
        float4 h0 = *(const float4*)&hs0[c * 52 + n0];
        float4 h1 = *(const float4*)&hs1[c * 52 + n0];
        float4 h2 = *(const float4*)&hs2[c * 52 + n0];
        float4 av = __ldg((const float4*)(g_A + c * 64 + p0));
        float4 bv = __ldg((const float4*)(g_B + c * 64 + p0));
        float4 cv = __ldg((const float4*)(g_C + c * 64 + p0));
        float h0v[4] = {h0.x, h0.y, h0.z, h0.w};
        float h1v[4] = {h1.x, h1.y, h1.z, h1.w};
        float h2v[4] = {h2.x, h2.y, h2.z, h2.w};
        float avv[4] = {av.x, av.y, av.z, av.w};
        float bvv[4] = {bv.x, bv.y, bv.z, bv.w};
        float cvv[4] = {cv.x, cv.y, cv.z, cv.w};
#pragma unroll
        for (int a = 0; a < 4; a++)
#pragma unroll
            for (int c2 = 0; c2 < 4; c2++) {
                acc[a][c2] = fmaf(h0v[a], avv[c2], acc[a][c2]);
                acc[a][c2] = fmaf(h1v[a], bvv[c2], acc[a][c2]);
                acc[a][c2] = fmaf(h2v[a], cvv[c2], acc[a][c2]);
            }
    }

#pragma unroll
    for (int a = 0; a < 4; a++) {
        int n = nb + n0 + a;
        if (n < NN)
            *(float4*)&hout[n * 64 + p0] = make_float4(acc[a][0], acc[a][1], acc[a][2], acc[a][3]);
    }
}

// ---------------- launch: fork {hist->scan->scatter} || {split->mid}, join, edge, node ----------------
extern "C" void kernel_launch(void* const* d_in, const int* in_sizes, int n_in,
                              void* d_out, int out_size) {
    const float* x     = (const float*)d_in[0];
    const float* ea    = (const float*)d_in[1];
    const float* hprev = (const float*)d_in[2];
    const int*   ei    = (const int*)  d_in[3];
    const float* w1    = (const float*)d_in[4];
    const float* b1    = (const float*)d_in[5];
    const float* w2    = (const float*)d_in[6];
    const float* b2    = (const float*)d_in[7];
    const float* root  = (const float*)d_in[8];
    const float* bias  = (const float*)d_in[9];
    const float* tw1   = (const float*)d_in[10];
    const float* tb1   = (const float*)d_in[11];
    const float* tw2   = (const float*)d_in[12];
    const float* tb2   = (const float*)d_in[13];
    const float* tw3   = (const float*)d_in[14];
    const float* tb3   = (const float*)d_in[15];
    const float* pw    = (const float*)d_in[16];
    const float* pb    = (const float*)d_in[17];

    float* hout  = (float*)d_out;            // [N,64]
    float* hhist = hout + NN * 64;           // [N,3,64]

    // one-time host-side resources (created on the pre-capture correctness call,
    // reused identically on every call — device work is identical each call)
    static cudaStream_t sB = nullptr;
    static cudaEvent_t evFork = nullptr, evJoin = nullptr;
    if (sB == nullptr) {
        cudaStreamCreateWithFlags(&sB, cudaStreamNonBlocking);
        cudaEventCreateWithFlags(&evFork, cudaEventDisableTiming);
        cudaEventCreateWithFlags(&evJoin, cudaEventDisableTiming);
    }

    // fork side stream B off the main (captured) stream
    cudaEventRecord(evFork, 0);
    cudaStreamWaitEvent(sB, evFork, 0);

    // chain A (main stream): edge ordering
    k_hist<<<391, 256>>>(ei);
    k_scan<<<1, 1024>>>();
    k_scatter<<<391, 256>>>(ei);

    // chain B (side stream): operand split -> v/H/ur/prep
    k_split<<<754, 256, 0, sB>>>(x, w2);
    k_mid<<<MB_P, 256, 0, sB>>>(x, b2, root, ea, w1, b1,
                                tw1, tb1, tw2, tb2, tw3, tb3, pw, pb);

    // join B back into main stream
    cudaEventRecord(evJoin, sB);
    cudaStreamWaitEvent(0, evJoin, 0);

    k_edge<<<5000, 128>>>();
    k_node<<<209, 192>>>(hprev, bias, hout, hhist);
}

// round 10
// speedup vs baseline: 1.3516x; 1.0014x over previous
#include <cuda_runtime.h>
#include <cuda_bf16.h>

#define NN 10000
#define EE 100000
#define KP 528          // kpairs per M row (K=1056 = 32*32 + 32)

// ---------------- device scratch (static allocations only) ----------------
__device__ __align__(16) float g_u[NN * 64];          // (dead but written by proven ur branch)
__device__ __align__(16) float g_r[NN * 64];
__device__ __align__(16) float g_agg[NN * 64];        // fully overwritten by k_gemm each run
__device__ __align__(16) float g_h[EE * 32];          // relu(ea@w1+b1)
__device__ int g_cntdst[NN];                          // zeroed at end of k_node
__device__ int g_start[NN + 1];
__device__ int g_cursor[NN];
__device__ int g_order[EE];
__device__ int g_osrc[EE];
__device__ __align__(16) float g_A[64 * 64];
__device__ __align__(16) float g_B[64 * 64];
__device__ __align__(16) float g_C[64 * 64];
__device__ __align__(16) float g_dv[64];
// split-bf16 operands: A = [M | Xbar] rows per node, B = [w2-perm | b2] cols
__device__ __align__(16) unsigned g_Ahi[NN * KP];     // 21 MB
__device__ __align__(16) unsigned g_Alo[NN * KP];
__device__ __align__(16) unsigned g_Bhi[KP * 64];
__device__ __align__(16) unsigned g_Blo[KP * 64];

__device__ __forceinline__ unsigned pack_bf16(__nv_bfloat16 a, __nv_bfloat16 b) {
    __nv_bfloat162 p = __halves2bfloat162(a, b);      // a in low 16 bits (even k)
    return *(unsigned*)&p;
}

__device__ __forceinline__ unsigned split_pair(float f0, float f1, float& l0, float& l1) {
    __nv_bfloat16 h0 = __float2bfloat16_rn(f0);
    __nv_bfloat16 h1 = __float2bfloat16_rn(f1);
    l0 = f0 - __bfloat162float(h0);
    l1 = f1 - __bfloat162float(h1);
    return pack_bf16(h0, h1);
}

__device__ __forceinline__ void mma_bf16(float* acc, const unsigned* a, unsigned b0, unsigned b1) {
    asm volatile(
        "mma.sync.aligned.m16n8k16.row.col.f32.bf16.bf16.f32 "
        "{%0,%1,%2,%3}, {%4,%5,%6,%7}, {%8,%9}, {%0,%1,%2,%3};"
        : "+f"(acc[0]), "+f"(acc[1]), "+f"(acc[2]), "+f"(acc[3])
        : "r"(a[0]), "r"(a[1]), "r"(a[2]), "r"(a[3]), "r"(b0), "r"(b1));
}

// ---------------- chain A-1: histogram of dst ----------------
__global__ void k_hist(const int* __restrict__ ei) {
    int e = blockIdx.x * 256 + threadIdx.x;
    if (e < EE) atomicAdd(&g_cntdst[ei[EE + e]], 1);
}

// ---------------- chain A-2: exclusive scan over dst counts ----------------
__global__ void k_scan() {
    __shared__ int wsum[32];
    int t = threadIdx.x;              // 1024
    int lane = t & 31, wid = t >> 5;
    const int CH = 10;
    int base = t * CH;
    int loc[CH];
    int s = 0;
#pragma unroll
    for (int k = 0; k < CH; k++) {
        int idx = base + k;
        int v = (idx < NN) ? g_cntdst[idx] : 0;   // do NOT zero: k_node needs counts
        loc[k] = s; s += v;
    }
    int inc = s;
#pragma unroll
    for (int off = 1; off < 32; off <<= 1) {
        int y = __shfl_up_sync(0xffffffffu, inc, off);
        if (lane >= off) inc += y;
    }
    if (lane == 31) wsum[wid] = inc;
    __syncthreads();
    if (wid == 0) {
        int ws = wsum[lane];
#pragma unroll
        for (int off = 1; off < 32; off <<= 1) {
            int y = __shfl_up_sync(0xffffffffu, ws, off);
            if (lane >= off) ws += y;
        }
        wsum[lane] = ws;
    }
    __syncthreads();
    int excl = inc - s + ((wid > 0) ? wsum[wid - 1] : 0);
#pragma unroll
    for (int k = 0; k < CH; k++) {
        int idx = base + k;
        if (idx < NN) {
            int st = excl + loc[k];
            g_start[idx] = st;
            g_cursor[idx] = st;
        }
    }
    if (t == 1023) g_start[NN] = wsum[31];
}

// ---------------- chain A-3: scatter edge ids grouped by dst ----------------
__global__ void k_scatter(const int* __restrict__ ei) {
    int e = blockIdx.x * 256 + threadIdx.x;
    if (e < EE) {
        int d = ei[EE + e];
        int pos = atomicAdd(&g_cursor[d], 1);
        g_order[pos] = e;
        g_osrc[pos] = ei[e];
    }
}

// ---------------- chain B: H-GEMM | u/r | prep | B-split ----------------
#define PB_H  1563
#define PB_R  (PB_H + 157)
#define PB_P  (PB_R + 16)
#define PB_S  (PB_P + 132)

__global__ void __launch_bounds__(256) k_prepB(
    const float* __restrict__ x,  const float* __restrict__ b2,
    const float* __restrict__ root, const float* __restrict__ w2,
    const float* __restrict__ ea, const float* __restrict__ w1,
    const float* __restrict__ b1,
    const float* __restrict__ tw1, const float* __restrict__ tb1,
    const float* __restrict__ tw2, const float* __restrict__ tb2,
    const float* __restrict__ tw3, const float* __restrict__ tb3,
    const float* __restrict__ pw,  const float* __restrict__ pb) {
    __shared__ __align__(16) float sbuf[6400];
    int b = blockIdx.x;
    int t = threadIdx.x;

    if (b < PB_H) {
        // ---- H GEMM: g_h[e][j] = relu(sum_d ea[e,d]*w1[d,j] + b1[j]) ----
        int base = b * 64;
        float* eas = sbuf;                       // [64*16]
        float* w1s = eas + 1024;                 // [512]
        float* b1s = w1s + 512;                  // [32]
        for (int q = t; q < 1024; q += 256) {
            int gidx = base * 16 + q;
            eas[q] = (gidx < EE * 16) ? ea[gidx] : 0.f;
        }
        for (int q = t; q < 512; q += 256) w1s[q] = w1[q];
        if (t < 32) b1s[t] = b1[t];
        __syncthreads();
        for (int q = t; q < 2048; q += 256) {
            int el = q >> 5, j = q & 31;
            int e = base + el;
            if (e < EE) {
                float acc = b1s[j];
#pragma unroll
                for (int d = 0; d < 16; d++)
                    acc = fmaf(eas[el * 16 + d], w1s[d * 32 + j], acc);
                g_h[e * 32 + j] = fmaxf(acc, 0.f);
            }
        }
    } else if (b < PB_R) {
        // ---- u/r GEMM (proven branch; u unused but harmless) ----
        int nb = (b - PB_H) * 64;
        float4* Wc = (float4*)sbuf;
        float*  xT = sbuf + 4096;
        const float4* b2f4 = (const float4*)b2;
        const float4* rtf4 = (const float4*)root;
#pragma unroll
        for (int q = 0; q < 4; q++) {
            int idx = q * 256 + t;
            int i = idx >> 5, c4 = idx & 31;
            Wc[idx] = (c4 < 16) ? b2f4[i * 16 + c4] : rtf4[i * 16 + (c4 - 16)];
        }
#pragma unroll
        for (int q = 0; q < 8; q++) {
            int f = q * 256 + t;
            int n = f >> 5, i = f & 31;
            xT[i * 64 + n] = (nb + n < NN) ? x[(nb + n) * 32 + i] : 0.f;
        }
        __syncthreads();

        int ng = t >> 5, cg = t & 31;
        float acc[8][4];
#pragma unroll
        for (int a = 0; a < 8; a++)
#pragma unroll
            for (int c = 0; c < 4; c++) acc[a][c] = 0.f;
#pragma unroll 8
        for (int i = 0; i < 32; i++) {
            float4 xa = *(const float4*)&xT[i * 64 + ng * 8];
            float4 xb = *(const float4*)&xT[i * 64 + ng * 8 + 4];
            float4 wv4 = Wc[i * 32 + cg];
            float xv[8] = {xa.x, xa.y, xa.z, xa.w, xb.x, xb.y, xb.z, xb.w};
            float wv[4] = {wv4.x, wv4.y, wv4.z, wv4.w};
#pragma unroll
            for (int a = 0; a < 8; a++)
#pragma unroll
                for (int c = 0; c < 4; c++) acc[a][c] = fmaf(xv[a], wv[c], acc[a][c]);
        }
        float4* u4 = (float4*)g_u;
        float4* r4 = (float4*)g_r;
#pragma unroll
        for (int a = 0; a < 8; a++) {
            int n = nb + ng * 8 + a;
            if (n < NN) {
                float4 val = make_float4(acc[a][0], acc[a][1], acc[a][2], acc[a][3]);
                if (cg < 16) u4[n * 16 + cg] = val;
                else         r4[n * 16 + (cg - 16)] = val;
            }
        }
    } else if (b < PB_P) {
        // ---- prep: fold TCN+proj into A,B,C,dv ----
        int q = (b - PB_R) * 256 + t;            // [0,4096)
        int c = q >> 6, p = q & 63;
        float a = 0.f, bb = 0.f, cc = 0.f;
        for (int o = 0; o < 64; o++) {
            float pw0 = __ldg(&pw[o * 64 + p]);
            float pw1 = __ldg(&pw[(64 + o) * 64 + p]);
            float pw2 = __ldg(&pw[(128 + o) * 64 + p]);
            bb = fmaf(__ldg(&tw1[o * 192 + c * 3 + 0]), pw0, bb);
            a  = fmaf(__ldg(&tw2[o * 192 + c * 3 + 0]), pw1, a);
            cc = fmaf(__ldg(&tw1[o * 192 + c * 3 + 1]), pw0, cc);
            cc = fmaf(__ldg(&tw2[o * 192 + c * 3 + 1]), pw1, cc);
            cc = fmaf(__ldg(&tw3[o * 192 + c * 3 + 1]), pw2, cc);
        }
        g_A[q] = a; g_B[q] = bb; g_C[q] = cc;
        if (b == PB_R && t < 64) {
            float d = pb[t];
            for (int o = 0; o < 64; o++) {
                d = fmaf(tb1[o], pw[o * 64 + t], d);
                d = fmaf(tb2[o], pw[(64 + o) * 64 + t], d);
                d = fmaf(tb3[o], pw[(128 + o) * 64 + t], d);
            }
            g_dv[t] = d;
        }
    } else {
        // ---- B-split: g_B{hi,lo}[kp*64 + c]; k=j*32+i -> w2[j, i*64+c]; k>=1024 -> b2 ----
        int idx = (b - PB_P) * 256 + t;          // [0, 33792)
        int kp = idx >> 6, c = idx & 63;
        float f0, f1;
        if (kp < 512) {
            int k0 = 2 * kp;
            int j = k0 >> 5, i0 = k0 & 31;
            f0 = w2[j * 2048 + i0 * 64 + c];
            f1 = w2[j * 2048 + (i0 + 1) * 64 + c];
        } else {
            int ip = kp - 512;
            f0 = b2[(2 * ip) * 64 + c];
            f1 = b2[(2 * ip + 1) * 64 + c];
        }
        float l0, l1;
        unsigned hi = split_pair(f0, f1, l0, l1);
        g_Bhi[kp * 64 + c] = hi;
        g_Blo[kp * 64 + c] = pack_bf16(__float2bfloat16_rn(l0), __float2bfloat16_rn(l1));
    }
}

// ---------------- join-1: M-build — warp per dst, outer-product accumulate ----------------
__global__ void __launch_bounds__(256) k_msg(const float* __restrict__ x) {
    __shared__ unsigned usm[8][512];
    int t = threadIdx.x;
    int w = t >> 5, l = t & 31;
    int d = blockIdx.x * 8 + w;               // 1250 blocks -> exactly NN
    int beg = g_start[d], end = g_start[d + 1];

    float acc[32];
#pragma unroll
    for (int i = 0; i < 32; i++) acc[i] = 0.f;
    float xbar = 0.f;

    float h0 = 0.f, x0 = 0.f, h1 = 0.f, x1 = 0.f;
    if (beg < end) {
        h0 = __ldg(&g_h[g_order[beg] * 32 + l]);
        x0 = __ldg(&x[g_osrc[beg] * 32 + l]);
    }
    if (beg + 1 < end) {
        h1 = __ldg(&g_h[g_order[beg + 1] * 32 + l]);
        x1 = __ldg(&x[g_osrc[beg + 1] * 32 + l]);
    }
    for (int p = beg; p < end; p++) {
        float h2 = 0.f, x2 = 0.f;
        if (p + 2 < end) {
            h2 = __ldg(&g_h[g_order[p + 2] * 32 + l]);
            x2 = __ldg(&x[g_osrc[p + 2] * 32 + l]);
        }
        xbar += x0;
#pragma unroll
        for (int i = 0; i < 32; i++)
            acc[i] = fmaf(h0, __shfl_sync(0xffffffffu, x0, i), acc[i]);
        h0 = h1; x0 = x1; h1 = h2; x1 = x2;
    }

    // split: hi to smem (transpose), lo packed into reused acc slots
#pragma unroll
    for (int ip = 0; ip < 16; ip++) {
        float l0, l1;
        unsigned hi = split_pair(acc[2 * ip], acc[2 * ip + 1], l0, l1);
        usm[w][l * 16 + ip] = hi;
        acc[ip] = __uint_as_float(
            (unsigned)pack_bf16(__float2bfloat16_rn(l0), __float2bfloat16_rn(l1)));
    }
    __syncwarp();
#pragma unroll
    for (int c = 0; c < 16; c++)
        g_Ahi[d * KP + c * 32 + l] = usm[w][c * 32 + l];
    __syncwarp();
#pragma unroll
    for (int ip = 0; ip < 16; ip++)
        usm[w][l * 16 + ip] = __float_as_uint(acc[ip]);
    __syncwarp();
#pragma unroll
    for (int c = 0; c < 16; c++)
        g_Alo[d * KP + c * 32 + l] = usm[w][c * 32 + l];

    // Xbar rows (kp 512..527): pairs gathered via shfl
    float xa = __shfl_sync(0xffffffffu, xbar, 2 * (l & 15));
    float xb = __shfl_sync(0xffffffffu, xbar, 2 * (l & 15) + 1);
    if (l < 16) {
        float l0, l1;
        unsigned hi = split_pair(xa, xb, l0, l1);
        g_Ahi[d * KP + 512 + l] = hi;
        g_Alo[d * KP + 512 + l] = pack_bf16(__float2bfloat16_rn(l0), __float2bfloat16_rn(l1));
    }
}

// ---------------- join-2: agg GEMM [NN,1056]@[1056,64] via split-bf16 mma ----------------
__global__ void __launch_bounds__(256) k_gemm() {
    __shared__ __align__(16) unsigned ash[64 * 20];
    __shared__ __align__(16) unsigned asl[64 * 20];
    __shared__ __align__(16) unsigned bsh[64 * 20];
    __shared__ __align__(16) unsigned bsl[64 * 20];
    int t = threadIdx.x;
    int nb = blockIdx.x * 64;                 // 157 blocks
    int w = t >> 5, l = t & 31;
    int wn = w >> 1, wc = w & 1;
    int r = wn * 16 + (l >> 2);
    int cq = l & 3;

    float acc[4][4];
#pragma unroll
    for (int ct = 0; ct < 4; ct++)
#pragma unroll
        for (int q = 0; q < 4; q++) acc[ct][q] = 0.f;

    for (int kt = 0; kt < 33; kt++) {
        int KB = kt * 16;
        __syncthreads();
#pragma unroll
        for (int q0 = 0; q0 < 4; q0++) {
            int q = q0 * 256 + t;             // [0,1024)
            int rr = q >> 4, kp = q & 15;
            int n = nb + rr;
            unsigned vh = 0, vl = 0;
            if (n < NN) {
                vh = g_Ahi[n * KP + KB + kp];
                vl = g_Alo[n * KP + KB + kp];
            }
            ash[rr * 20 + kp] = vh;
            asl[rr * 20 + kp] = vl;
        }
#pragma unroll
        for (int q0 = 0; q0 < 4; q0++) {
            int q = q0 * 256 + t;
            int kp = q >> 6, c = q & 63;
            bsh[c * 20 + kp] = g_Bhi[(KB + kp) * 64 + c];
            bsl[c * 20 + kp] = g_Blo[(KB + kp) * 64 + c];
        }
        __syncthreads();

#pragma unroll
        for (int ks = 0; ks < 2; ks++) {
            int kb = ks * 8 + cq;
            unsigned ah[4], al[4];
            ah[0] = ash[r * 20 + kb];       ah[1] = ash[(r + 8) * 20 + kb];
            ah[2] = ash[r * 20 + kb + 4];   ah[3] = ash[(r + 8) * 20 + kb + 4];
            al[0] = asl[r * 20 + kb];       al[1] = asl[(r + 8) * 20 + kb];
            al[2] = asl[r * 20 + kb + 4];   al[3] = asl[(r + 8) * 20 + kb + 4];
#pragma unroll
            for (int ct = 0; ct < 4; ct++) {
                int c = wc * 32 + ct * 8 + (l >> 2);
                unsigned bh0 = bsh[c * 20 + kb], bh1 = bsh[c * 20 + kb + 4];
                unsigned bl0 = bsl[c * 20 + kb], bl1 = bsl[c * 20 + kb + 4];
                mma_bf16(acc[ct], ah, bh0, bh1);
                mma_bf16(acc[ct], ah, bl0, bl1);
                mma_bf16(acc[ct], al, bh0, bh1);
            }
        }
    }

    int rr0 = nb + wn * 16 + (l >> 2);
#pragma unroll
    for (int ct = 0; ct < 4; ct++) {
        int col = wc * 32 + ct * 8 + 2 * cq;
        if (rr0 < NN)
            *(float2*)&g_agg[rr0 * 64 + col] = make_float2(acc[ct][0], acc[ct][1]);
        if (rr0 + 8 < NN)
            *(float2*)&g_agg[(rr0 + 8) * 64 + col] = make_float2(acc[ct][2], acc[ct][3]);
    }
}

// ---------------- final: node kernel ----------------
__global__ void k_node(const float* __restrict__ hprev, const float* __restrict__ bias,
                       float* __restrict__ hout, float* __restrict__ hhist) {
    __shared__ float hs0[64 * 52];
    __shared__ float hs1[64 * 52];
    __shared__ float hs2[64 * 52];
    int t = threadIdx.x;              // 192 threads
    int nb = blockIdx.x * 48;

    for (int s = 0; s < 16; s++) {
        int q = s * 192 + t;
        int nl = q >> 6, o = q & 63;
        int n = nb + nl;
        float hp1 = 0.f, hp2 = 0.f, hg = 0.f;
        if (n < NN) {
            hp1 = hprev[n * 192 + 64 + o];
            hp2 = hprev[n * 192 + 128 + o];
            float cnt = (float)g_cntdst[n];
            float mean = g_agg[n * 64 + o] / fmaxf(cnt, 1.f);
            hg = fmaxf(mean + g_r[n * 64 + o] + bias[o], 0.f);
            hhist[n * 192 + o] = hp1;
            hhist[n * 192 + 64 + o] = hp2;
            hhist[n * 192 + 128 + o] = hg;
        }
        hs0[o * 52 + nl] = hp1;
        hs1[o * 52 + nl] = hp2;
        hs2[o * 52 + nl] = hg;
    }
    __syncthreads();

    // restore invariant for next replay (agg is overwritten by k_gemm; only cnt needs reset)
    if (t < 48 && nb + t < NN) g_cntdst[nb + t] = 0;

    int tn = t % 12, tp = t / 12;
    int n0 = tn * 4, p0 = tp * 4;
    float4 dv = *(const float4*)&g_dv[p0];
    float acc[4][4];
#pragma unroll
    for (int a = 0; a < 4; a++) {
        acc[a][0] = dv.x; acc[a][1] = dv.y; acc[a][2] = dv.z; acc[a][3] = dv.w;
    }

#pragma unroll 8
    for (int c = 0; c < 64; c++) {
        float4 h0 = *(const float4*)&hs0[c * 52 + n0];
        float4 h1 = *(const float4*)&hs1[c * 52 + n0];
        float4 h2 = *(const float4*)&hs2[c * 52 + n0];
        float4 av = __ldg((const float4*)(g_A + c * 64 + p0));
        float4 bv = __ldg((const float4*)(g_B + c * 64 + p0));
        float4 cv = __ldg((const float4*)(g_C + c * 64 + p0));
        float h0v[4] = {h0.x, h0.y, h0.z, h0.w};
        float h1v[4] = {h1.x, h1.y, h1.z, h1.w};
        float h2v[4] = {h2.x, h2.y, h2.z, h2.w};
        float avv[4] = {av.x, av.y, av.z, av.w};
        float bvv[4] = {bv.x, bv.y, bv.z, bv.w};
        float cvv[4] = {cv.x, cv.y, cv.z, cv.w};
#pragma unroll
        for (int a = 0; a < 4; a++)
#pragma unroll
            for (int c2 = 0; c2 < 4; c2++) {
                acc[a][c2] = fmaf(h0v[a], avv[c2], acc[a][c2]);
                acc[a][c2] = fmaf(h1v[a], bvv[c2], acc[a][c2]);
                acc[a][c2] = fmaf(h2v[a], cvv[c2], acc[a][c2]);
            }
    }

#pragma unroll
    for (int a = 0; a < 4; a++) {
        int n = nb + n0 + a;
        if (n < NN)
            *(float4*)&hout[n * 64 + p0] = make_float4(acc[a][0], acc[a][1], acc[a][2], acc[a][3]);
    }
}

// ---------------- launch: fork {hist->scan->scatter} || {prepB}, join, msg, gemm, node ----------------
extern "C" void kernel_launch(void* const* d_in, const int* in_sizes, int n_in,
                              void* d_out, int out_size) {
    const float* x     = (const float*)d_in[0];
    const float* ea    = (const float*)d_in[1];
    const float* hprev = (const float*)d_in[2];
    const int*   ei    = (const int*)  d_in[3];
    const float* w1    = (const float*)d_in[4];
    const float* b1    = (const float*)d_in[5];
    const float* w2    = (const float*)d_in[6];
    const float* b2    = (const float*)d_in[7];
    const float* root  = (const float*)d_in[8];
    const float* bias  = (const float*)d_in[9];
    const float* tw1   = (const float*)d_in[10];
    const float* tb1   = (const float*)d_in[11];
    const float* tw2   = (const float*)d_in[12];
    const float* tb2   = (const float*)d_in[13];
    const float* tw3   = (const float*)d_in[14];
    const float* tb3   = (const float*)d_in[15];
    const float* pw    = (const float*)d_in[16];
    const float* pb    = (const float*)d_in[17];

    float* hout  = (float*)d_out;            // [N,64]
    float* hhist = hout + NN * 64;           // [N,3,64]

    static cudaStream_t sB = nullptr;
    static cudaEvent_t evFork = nullptr, evJoin = nullptr;
    if (sB == nullptr) {
        cudaStreamCreateWithFlags(&sB, cudaStreamNonBlocking);
        cudaEventCreateWithFlags(&evFork, cudaEventDisableTiming);
        cudaEventCreateWithFlags(&evJoin, cudaEventDisableTiming);
    }

    cudaEventRecord(evFork, 0);
    cudaStreamWaitEvent(sB, evFork, 0);

    // chain A (main): dst ordering
    k_hist<<<391, 256>>>(ei);
    k_scan<<<1, 1024>>>();
    k_scatter<<<391, 256>>>(ei);

    // chain B (side): H-GEMM, r, ABC prep, B-split
    k_prepB<<<PB_S, 256, 0, sB>>>(x, b2, root, w2, ea, w1, b1,
                                  tw1, tb1, tw2, tb2, tw3, tb3, pw, pb);

    cudaEventRecord(evJoin, sB);
    cudaStreamWaitEvent(0, evJoin, 0);

    k_msg<<<1250, 256>>>(x);
    k_gemm<<<157, 256>>>();
    k_node<<<209, 192>>>(hprev, bias, hout, hhist);
}

// round 11
// speedup vs baseline: 1.5367x; 1.1370x over previous
#include <cuda_runtime.h>
#include <cuda_bf16.h>

#define NN 10000
#define EE 100000
#define KP 528          // kpairs per M row (K=1056 = 32*32 + 32)

// ---------------- device scratch (static allocations only) ----------------
__device__ __align__(16) float g_u[NN * 64];          // dead output of proven ur branch
__device__ __align__(16) float g_r[NN * 64];
__device__ __align__(16) float g_h[EE * 32];          // relu(ea@w1+b1)
__device__ int g_cntdst[NN];                          // zeroed in k_gemmnode after use
__device__ int g_start[NN + 1];
__device__ int g_cursor[NN];
__device__ int g_order[EE];
__device__ int g_osrc[EE];
__device__ __align__(16) float g_A[64 * 64];
__device__ __align__(16) float g_B[64 * 64];
__device__ __align__(16) float g_C[64 * 64];
__device__ __align__(16) float g_dv[64];
// split-bf16 operands: A = [M | Xbar] rows per node, B = [w2-perm | b2] cols
__device__ __align__(16) unsigned g_Ahi[NN * KP];
__device__ __align__(16) unsigned g_Alo[NN * KP];
__device__ __align__(16) unsigned g_Bhi[KP * 64];
__device__ __align__(16) unsigned g_Blo[KP * 64];

__device__ __forceinline__ unsigned pack_bf16(__nv_bfloat16 a, __nv_bfloat16 b) {
    __nv_bfloat162 p = __halves2bfloat162(a, b);      // a in low 16 bits (even k)
    return *(unsigned*)&p;
}

__device__ __forceinline__ unsigned split_pair(float f0, float f1, float& l0, float& l1) {
    __nv_bfloat16 h0 = __float2bfloat16_rn(f0);
    __nv_bfloat16 h1 = __float2bfloat16_rn(f1);
    l0 = f0 - __bfloat162float(h0);
    l1 = f1 - __bfloat162float(h1);
    return pack_bf16(h0, h1);
}

__device__ __forceinline__ void mma_bf16(float* acc, const unsigned* a, unsigned b0, unsigned b1) {
    asm volatile(
        "mma.sync.aligned.m16n8k16.row.col.f32.bf16.bf16.f32 "
        "{%0,%1,%2,%3}, {%4,%5,%6,%7}, {%8,%9}, {%0,%1,%2,%3};"
        : "+f"(acc[0]), "+f"(acc[1]), "+f"(acc[2]), "+f"(acc[3])
        : "r"(a[0]), "r"(a[1]), "r"(a[2]), "r"(a[3]), "r"(b0), "r"(b1));
}

// ---------------- chain A-1: histogram of dst ----------------
__global__ void k_hist(const int* __restrict__ ei) {
    int e = blockIdx.x * 256 + threadIdx.x;
    if (e < EE) atomicAdd(&g_cntdst[ei[EE + e]], 1);
}

// ---------------- chain A-2: exclusive scan over dst counts ----------------
__global__ void k_scan() {
    __shared__ int wsum[32];
    int t = threadIdx.x;              // 1024
    int lane = t & 31, wid = t >> 5;
    const int CH = 10;
    int base = t * CH;
    int loc[CH];
    int s = 0;
#pragma unroll
    for (int k = 0; k < CH; k++) {
        int idx = base + k;
        int v = (idx < NN) ? g_cntdst[idx] : 0;   // counts still needed later
        loc[k] = s; s += v;
    }
    int inc = s;
#pragma unroll
    for (int off = 1; off < 32; off <<= 1) {
        int y = __shfl_up_sync(0xffffffffu, inc, off);
        if (lane >= off) inc += y;
    }
    if (lane == 31) wsum[wid] = inc;
    __syncthreads();
    if (wid == 0) {
        int ws = wsum[lane];
#pragma unroll
        for (int off = 1; off < 32; off <<= 1) {
            int y = __shfl_up_sync(0xffffffffu, ws, off);
            if (lane >= off) ws += y;
        }
        wsum[lane] = ws;
    }
    __syncthreads();
    int excl = inc - s + ((wid > 0) ? wsum[wid - 1] : 0);
#pragma unroll
    for (int k = 0; k < CH; k++) {
        int idx = base + k;
        if (idx < NN) {
            int st = excl + loc[k];
            g_start[idx] = st;
            g_cursor[idx] = st;
        }
    }
    if (t == 1023) g_start[NN] = wsum[31];
}

// ---------------- chain A-3: scatter edge ids grouped by dst ----------------
__global__ void k_scatter(const int* __restrict__ ei) {
    int e = blockIdx.x * 256 + threadIdx.x;
    if (e < EE) {
        int d = ei[EE + e];
        int pos = atomicAdd(&g_cursor[d], 1);
        g_order[pos] = e;
        g_osrc[pos] = ei[e];
    }
}

// ---------------- chain B: H-GEMM | u/r | prep | B-split ----------------
#define PB_H  1563
#define PB_R  (PB_H + 157)
#define PB_P  (PB_R + 16)
#define PB_S  (PB_P + 132)

__global__ void __launch_bounds__(256) k_prepB(
    const float* __restrict__ x,  const float* __restrict__ b2,
    const float* __restrict__ root, const float* __restrict__ w2,
    const float* __restrict__ ea, const float* __restrict__ w1,
    const float* __restrict__ b1,
    const float* __restrict__ tw1, const float* __restrict__ tb1,
    const float* __restrict__ tw2, const float* __restrict__ tb2,
    const float* __restrict__ tw3, const float* __restrict__ tb3,
    const float* __restrict__ pw,  const float* __restrict__ pb) {
    __shared__ __align__(16) float sbuf[6400];
    int b = blockIdx.x;
    int t = threadIdx.x;

    if (b < PB_H) {
        // ---- H GEMM: g_h[e][j] = relu(sum_d ea[e,d]*w1[d,j] + b1[j]) ----
        // MIO-lean: w1 column hoisted to regs, eas reads are warp-broadcast.
        int base = b * 64;
        float* eas = sbuf;                       // [64*16]
        float* w1s = eas + 1024;                 // [512]
        float* b1s = w1s + 512;                  // [32]
        for (int q = t; q < 1024; q += 256) {
            int gidx = base * 16 + q;
            eas[q] = (gidx < EE * 16) ? ea[gidx] : 0.f;
        }
        for (int q = t; q < 512; q += 256) w1s[q] = w1[q];
        if (t < 32) b1s[t] = b1[t];
        __syncthreads();

        int j = t & 31;                          // per-thread output col
        int elb = (t >> 5) * 8;                  // 8 edges per thread
        float w1c[16];
#pragma unroll
        for (int d = 0; d < 16; d++) w1c[d] = w1s[d * 32 + j];
        float bj = b1s[j];
#pragma unroll
        for (int k = 0; k < 8; k++) {
            int el = elb + k;
            int e = base + el;
            float acc = bj;
#pragma unroll
            for (int d = 0; d < 16; d++)
                acc = fmaf(eas[el * 16 + d], w1c[d], acc);   // broadcast LDS
            if (e < EE) g_h[e * 32 + j] = fmaxf(acc, 0.f);
        }
    } else if (b < PB_R) {
        // ---- u/r GEMM (proven branch) ----
        int nb = (b - PB_H) * 64;
        float4* Wc = (float4*)sbuf;
        float*  xT = sbuf + 4096;
        const float4* b2f4 = (const float4*)b2;
        const float4* rtf4 = (const float4*)root;
#pragma unroll
        for (int q = 0; q < 4; q++) {
            int idx = q * 256 + t;
            int i = idx >> 5, c4 = idx & 31;
            Wc[idx] = (c4 < 16) ? b2f4[i * 16 + c4] : rtf4[i * 16 + (c4 - 16)];
        }
#pragma unroll
        for (int q = 0; q < 8; q++) {
            int f = q * 256 + t;
            int n = f >> 5, i = f & 31;
            xT[i * 64 + n] = (nb + n < NN) ? x[(nb + n) * 32 + i] : 0.f;
        }
        __syncthreads();

        int ng = t >> 5, cg = t & 31;
        float acc[8][4];
#pragma unroll
        for (int a = 0; a < 8; a++)
#pragma unroll
            for (int c = 0; c < 4; c++) acc[a][c] = 0.f;
#pragma unroll 8
        for (int i = 0; i < 32; i++) {
            float4 xa = *(const float4*)&xT[i * 64 + ng * 8];
            float4 xb = *(const float4*)&xT[i * 64 + ng * 8 + 4];
            float4 wv4 = Wc[i * 32 + cg];
            float xv[8] = {xa.x, xa.y, xa.z, xa.w, xb.x, xb.y, xb.z, xb.w};
            float wv[4] = {wv4.x, wv4.y, wv4.z, wv4.w};
#pragma unroll
            for (int a = 0; a < 8; a++)
#pragma unroll
                for (int c = 0; c < 4; c++) acc[a][c] = fmaf(xv[a], wv[c], acc[a][c]);
        }
        float4* u4 = (float4*)g_u;
        float4* r4 = (float4*)g_r;
#pragma unroll
        for (int a = 0; a < 8; a++) {
            int n = nb + ng * 8 + a;
            if (n < NN) {
                float4 val = make_float4(acc[a][0], acc[a][1], acc[a][2], acc[a][3]);
                if (cg < 16) u4[n * 16 + cg] = val;
                else         r4[n * 16 + (cg - 16)] = val;
            }
        }
    } else if (b < PB_P) {
        // ---- prep: fold TCN+proj into A,B,C,dv ----
        int q = (b - PB_R) * 256 + t;            // [0,4096)
        int c = q >> 6, p = q & 63;
        float a = 0.f, bb = 0.f, cc = 0.f;
        for (int o = 0; o < 64; o++) {
            float pw0 = __ldg(&pw[o * 64 + p]);
            float pw1 = __ldg(&pw[(64 + o) * 64 + p]);
            float pw2 = __ldg(&pw[(128 + o) * 64 + p]);
            bb = fmaf(__ldg(&tw1[o * 192 + c * 3 + 0]), pw0, bb);
            a  = fmaf(__ldg(&tw2[o * 192 + c * 3 + 0]), pw1, a);
            cc = fmaf(__ldg(&tw1[o * 192 + c * 3 + 1]), pw0, cc);
            cc = fmaf(__ldg(&tw2[o * 192 + c * 3 + 1]), pw1, cc);
            cc = fmaf(__ldg(&tw3[o * 192 + c * 3 + 1]), pw2, cc);
        }
        g_A[q] = a; g_B[q] = bb; g_C[q] = cc;
        if (b == PB_R && t < 64) {
            float d = pb[t];
            for (int o = 0; o < 64; o++) {
                d = fmaf(tb1[o], pw[o * 64 + t], d);
                d = fmaf(tb2[o], pw[(64 + o) * 64 + t], d);
                d = fmaf(tb3[o], pw[(128 + o) * 64 + t], d);
            }
            g_dv[t] = d;
        }
    } else {
        // ---- B-split ----
        int idx = (b - PB_P) * 256 + t;          // [0, 33792)
        int kp = idx >> 6, c = idx & 63;
        float f0, f1;
        if (kp < 512) {
            int k0 = 2 * kp;
            int j = k0 >> 5, i0 = k0 & 31;
            f0 = w2[j * 2048 + i0 * 64 + c];
            f1 = w2[j * 2048 + (i0 + 1) * 64 + c];
        } else {
            int ip = kp - 512;
            f0 = b2[(2 * ip) * 64 + c];
            f1 = b2[(2 * ip + 1) * 64 + c];
        }
        float l0, l1;
        unsigned hi = split_pair(f0, f1, l0, l1);
        g_Bhi[kp * 64 + c] = hi;
        g_Blo[kp * 64 + c] = pack_bf16(__float2bfloat16_rn(l0), __float2bfloat16_rn(l1));
    }
}

// ---------------- join-1: M-build — warp per dst, LDS.128 broadcast (no shfl) ----------------
__global__ void __launch_bounds__(256) k_msg(const float* __restrict__ x) {
    __shared__ __align__(16) float xs[8][2][32];   // per-warp double-buffered x row
    __shared__ unsigned trs[8][544];               // transpose staging, pad 17
    int t = threadIdx.x;
    int w = t >> 5, l = t & 31;
    int d = blockIdx.x * 8 + w;               // 1250 blocks -> exactly NN
    int beg = g_start[d], end = g_start[d + 1];

    float acc[32];
#pragma unroll
    for (int i = 0; i < 32; i++) acc[i] = 0.f;
    float xbar = 0.f;

    float h0 = 0.f, x0 = 0.f, h1 = 0.f, x1 = 0.f;
    if (beg < end) {
        h0 = __ldg(&g_h[g_order[beg] * 32 + l]);
        x0 = __ldg(&x[g_osrc[beg] * 32 + l]);
    }
    if (beg + 1 < end) {
        h1 = __ldg(&g_h[g_order[beg + 1] * 32 + l]);
        x1 = __ldg(&x[g_osrc[beg + 1] * 32 + l]);
    }
    for (int p = beg; p < end; p++) {
        xs[w][p & 1][l] = x0;
        __syncwarp();
        float h2 = 0.f, x2 = 0.f;
        if (p + 2 < end) {
            h2 = __ldg(&g_h[g_order[p + 2] * 32 + l]);
            x2 = __ldg(&x[g_osrc[p + 2] * 32 + l]);
        }
        xbar += x0;
        const float4* xv4 = (const float4*)&xs[w][p & 1][0];
#pragma unroll
        for (int q = 0; q < 8; q++) {
            float4 f = xv4[q];                 // broadcast LDS.128
            acc[4 * q + 0] = fmaf(h0, f.x, acc[4 * q + 0]);
            acc[4 * q + 1] = fmaf(h0, f.y, acc[4 * q + 1]);
            acc[4 * q + 2] = fmaf(h0, f.z, acc[4 * q + 2]);
            acc[4 * q + 3] = fmaf(h0, f.w, acc[4 * q + 3]);
        }
        h0 = h1; x0 = x1; h1 = h2; x1 = x2;
        __syncwarp();                          // protect slot reuse at p+2
    }

    // split + transpose: hi pass then lo pass (pad-17, conflict-free)
    unsigned lobits[16];
#pragma unroll
    for (int ip = 0; ip < 16; ip++) {
        float l0, l1;
        unsigned hi = split_pair(acc[2 * ip], acc[2 * ip + 1], l0, l1);
        trs[w][l * 17 + ip] = hi;
        lobits[ip] = pack_bf16(__float2bfloat16_rn(l0), __float2bfloat16_rn(l1));
    }
    __syncwarp();
#pragma unroll
    for (int c = 0; c < 16; c++) {
        int q = c * 32 + l;
        g_Ahi[d * KP + q] = trs[w][(q >> 4) * 17 + (q & 15)];
    }
    __syncwarp();
#pragma unroll
    for (int ip = 0; ip < 16; ip++) trs[w][l * 17 + ip] = lobits[ip];
    __syncwarp();
#pragma unroll
    for (int c = 0; c < 16; c++) {
        int q = c * 32 + l;
        g_Alo[d * KP + q] = trs[w][(q >> 4) * 17 + (q & 15)];
    }

    // Xbar rows (kp 512..527)
    float xa = __shfl_sync(0xffffffffu, xbar, 2 * (l & 15));
    float xb = __shfl_sync(0xffffffffu, xbar, 2 * (l & 15) + 1);
    if (l < 16) {
        float l0, l1;
        unsigned hi = split_pair(xa, xb, l0, l1);
        g_Ahi[d * KP + 512 + l] = hi;
        g_Alo[d * KP + 512 + l] = pack_bf16(__float2bfloat16_rn(l0), __float2bfloat16_rn(l1));
    }
}

// ---------------- join-2: fused agg-GEMM + node epilogue, 32 rows/block ----------------
__global__ void __launch_bounds__(256) k_gemmnode(
    const float* __restrict__ hprev, const float* __restrict__ bias,
    float* __restrict__ hout, float* __restrict__ hhist) {
    __shared__ __align__(16) float ubuf[6720];     // 26.9 KB union
    unsigned* ash = (unsigned*)ubuf;               // [32*20]
    unsigned* asl = ash + 640;
    unsigned* bsh = ash + 1280;                    // [64*20]
    unsigned* bsl = ash + 2560;
    int t = threadIdx.x;
    int nb = blockIdx.x * 32;                      // 313 blocks
    int w = t >> 5, l = t & 31;
    int wn = w >> 2, wc = w & 3;
    int rl0 = wn * 16 + (l >> 2);                  // local rows rl0, rl0+8
    int cq = l & 3;

    float acc[2][4];
#pragma unroll
    for (int ct = 0; ct < 2; ct++)
#pragma unroll
        for (int q = 0; q < 4; q++) acc[ct][q] = 0.f;

    for (int kt = 0; kt < 33; kt++) {
        int KB = kt * 16;
        __syncthreads();
#pragma unroll
        for (int q0 = 0; q0 < 2; q0++) {
            int q = q0 * 256 + t;                  // [0,512)
            int rr = q >> 4, kp = q & 15;
            int n = nb + rr;
            unsigned vh = 0, vl = 0;
            if (n < NN) {
                vh = g_Ahi[n * KP + KB + kp];
                vl = g_Alo[n * KP + KB + kp];
            }
            ash[rr * 20 + kp] = vh;
            asl[rr * 20 + kp] = vl;
        }
#pragma unroll
        for (int q0 = 0; q0 < 4; q0++) {
            int q = q0 * 256 + t;                  // [0,1024)
            int kp = q >> 6, c = q & 63;
            bsh[c * 20 + kp] = g_Bhi[(KB + kp) * 64 + c];
            bsl[c * 20 + kp] = g_Blo[(KB + kp) * 64 + c];
        }
        __syncthreads();

#pragma unroll
        for (int ks = 0; ks < 2; ks++) {
            int kb = ks * 8 + cq;
            unsigned ah[4], al[4];
            ah[0] = ash[rl0 * 20 + kb];       ah[1] = ash[(rl0 + 8) * 20 + kb];
            ah[2] = ash[rl0 * 20 + kb + 4];   ah[3] = ash[(rl0 + 8) * 20 + kb + 4];
            al[0] = asl[rl0 * 20 + kb];       al[1] = asl[(rl0 + 8) * 20 + kb];
            al[2] = asl[rl0 * 20 + kb + 4];   al[3] = asl[(rl0 + 8) * 20 + kb + 4];
#pragma unroll
            for (int ct = 0; ct < 2; ct++) {
                int c = wc * 16 + ct * 8 + (l >> 2);
                unsigned bh0 = bsh[c * 20 + kb], bh1 = bsh[c * 20 + kb + 4];
                unsigned bl0 = bsl[c * 20 + kb], bl1 = bsl[c * 20 + kb + 4];
                mma_bf16(acc[ct], ah, bh0, bh1);
                mma_bf16(acc[ct], ah, bl0, bl1);
                mma_bf16(acc[ct], al, bh0, bh1);
            }
        }
    }
    __syncthreads();                               // phase-1 smem dead

    float* hs0 = ubuf;                             // [64 cols][35]
    float* hs1 = ubuf + 2240;
    float* hs2 = ubuf + 4480;

    // phase 2a: hg from fragments (agg never leaves registers)
    {
        int rr0 = nb + rl0, rr1 = rr0 + 8;
        float c0 = (rr0 < NN) ? fmaxf((float)g_cntdst[rr0], 1.f) : 1.f;
        float c1 = (rr1 < NN) ? fmaxf((float)g_cntdst[rr1], 1.f) : 1.f;
#pragma unroll
        for (int ct = 0; ct < 2; ct++) {
            int col = wc * 16 + ct * 8 + 2 * cq;
#pragma unroll
            for (int bq = 0; bq < 2; bq++) {
                int cc = col + bq;
                float bi = __ldg(&bias[cc]);
                if (rr0 < NN) {
                    float hg = fmaxf(acc[ct][bq] / c0 + __ldg(&g_r[rr0 * 64 + cc]) + bi, 0.f);
                    hs2[cc * 35 + rl0] = hg;
                    hhist[rr0 * 192 + 128 + cc] = hg;
                }
                if (rr1 < NN) {
                    float hg = fmaxf(acc[ct][2 + bq] / c1 + __ldg(&g_r[rr1 * 64 + cc]) + bi, 0.f);
                    hs2[cc * 35 + rl0 + 8] = hg;
                    hhist[rr1 * 192 + 128 + cc] = hg;
                }
            }
        }
    }
    // phase 2b: hp1/hp2 copy + hhist
#pragma unroll
    for (int s = 0; s < 8; s++) {
        int q = s * 256 + t;                       // [0,2048)
        int rl = q >> 6, o = q & 63;
        int n = nb + rl;
        float hp1 = 0.f, hp2 = 0.f;
        if (n < NN) {
            hp1 = hprev[n * 192 + 64 + o];
            hp2 = hprev[n * 192 + 128 + o];
            hhist[n * 192 + o] = hp1;
            hhist[n * 192 + 64 + o] = hp2;
        }
        hs0[o * 35 + rl] = hp1;
        hs1[o * 35 + rl] = hp2;
    }
    if (t < 32 && nb + t < NN) g_cntdst[nb + t] = 0;   // restore invariant
    __syncthreads();

    // phase 3: node GEMM (32 rows x 64 cols)
    int tn = t & 7, tp = t >> 3;                   // rows tn*4.., cols tp*2..
    float2 dv = *(const float2*)&g_dv[tp * 2];
    float a2[4][2];
#pragma unroll
    for (int a = 0; a < 4; a++) { a2[a][0] = dv.x; a2[a][1] = dv.y; }

#pragma unroll 8
    for (int c = 0; c < 64; c++) {
        float h0v[4], h1v[4], h2v[4];
#pragma unroll
        for (int a = 0; a < 4; a++) {
            h0v[a] = hs0[c * 35 + tn * 4 + a];
            h1v[a] = hs1[c * 35 + tn * 4 + a];
            h2v[a] = hs2[c * 35 + tn * 4 + a];
        }
        float2 av = __ldg((const float2*)&g_A[c * 64 + tp * 2]);
        float2 bv = __ldg((const float2*)&g_B[c * 64 + tp * 2]);
        float2 cv = __ldg((const float2*)&g_C[c * 64 + tp * 2]);
#pragma unroll
        for (int a = 0; a < 4; a++) {
            a2[a][0] = fmaf(h0v[a], av.x, a2[a][0]);
            a2[a][0] = fmaf(h1v[a], bv.x, a2[a][0]);
            a2[a][0] = fmaf(h2v[a], cv.x, a2[a][0]);
            a2[a][1] = fmaf(h0v[a], av.y, a2[a][1]);
            a2[a][1] = fmaf(h1v[a], bv.y, a2[a][1]);
            a2[a][1] = fmaf(h2v[a], cv.y, a2[a][1]);
        }
    }
#pragma unroll
    for (int a = 0; a < 4; a++) {
        int n = nb + tn * 4 + a;
        if (n < NN)
            *(float2*)&hout[n * 64 + tp * 2] = make_float2(a2[a][0], a2[a][1]);
    }
}

// ---------------- launch: fork {hist->scan->scatter} || {prepB}, join, msg, gemmnode ----------------
extern "C" void kernel_launch(void* const* d_in, const int* in_sizes, int n_in,
                              void* d_out, int out_size) {
    const float* x     = (const float*)d_in[0];
    const float* ea    = (const float*)d_in[1];
    const float* hprev = (const float*)d_in[2];
    const int*   ei    = (const int*)  d_in[3];
    const float* w1    = (const float*)d_in[4];
    const float* b1    = (const float*)d_in[5];
    const float* w2    = (const float*)d_in[6];
    const float* b2    = (const float*)d_in[7];
    const float* root  = (const float*)d_in[8];
    const float* bias  = (const float*)d_in[9];
    const float* tw1   = (const float*)d_in[10];
    const float* tb1   = (const float*)d_in[11];
    const float* tw2   = (const float*)d_in[12];
    const float* tb2   = (const float*)d_in[13];
    const float* tw3   = (const float*)d_in[14];
    const float* tb3   = (const float*)d_in[15];
    const float* pw    = (const float*)d_in[16];
    const float* pb    = (const float*)d_in[17];

    float* hout  = (float*)d_out;            // [N,64]
    float* hhist = hout + NN * 64;           // [N,3,64]

    static cudaStream_t sB = nullptr;
    static cudaEvent_t evFork = nullptr, evJoin = nullptr;
    if (sB == nullptr) {
        cudaStreamCreateWithFlags(&sB, cudaStreamNonBlocking);
        cudaEventCreateWithFlags(&evFork, cudaEventDisableTiming);
        cudaEventCreateWithFlags(&evJoin, cudaEventDisableTiming);
    }

    cudaEventRecord(evFork, 0);
    cudaStreamWaitEvent(sB, evFork, 0);

    // chain A (main): dst ordering
    k_hist<<<391, 256>>>(ei);
    k_scan<<<1, 1024>>>();
    k_scatter<<<391, 256>>>(ei);

    // chain B (side): H-GEMM, r, ABC prep, B-split
    k_prepB<<<PB_S, 256, 0, sB>>>(x, b2, root, w2, ea, w1, b1,
                                  tw1, tb1, tw2, tb2, tw3, tb3, pw, pb);

    cudaEventRecord(evJoin, sB);
    cudaStreamWaitEvent(0, evJoin, 0);

    k_msg<<<1250, 256>>>(x);
    k_gemmnode<<<313, 256>>>(hprev, bias, hout, hhist);
}